// round 6
// baseline (speedup 1.0000x reference)
#include <cuda_runtime.h>
#include <cuda_fp16.h>
#include <math.h>

#define NN 50000
#define NE 800000
#define ETOT 850000      // NE + NN self loops
#define FIN 128
#define D1 128           // NH*HID
#define NH 4
#define HID 32
#define NC 40
#define NEG_SLOPE 0.2f
#define CSRB 592         // persistent CSR blocks (4 per SM, all co-resident)

typedef unsigned long long ull;

// ---------------- scratch (device globals) ----------------
__device__ __align__(16) __half2 g_h1h[NN * 64];     // x@W1 in fp16 (gather stream)
__device__ __align__(16) float g_esrc1[NN * 4];
__device__ __align__(16) float g_edst1[NN * 4];
__device__ __align__(16) float g_agg1[NN * D1];      // layer1 out fp32 (GEMM2 A)
__device__ __align__(16) __half g_h2h[NN * NC];      // h@W2 in fp16 (gather stream)
__device__ float g_esrc2[NN];
__device__ float g_edst2[NN];
// global max of e_src; reset protocol:
//   g_gmax1 reset by gat2 (end of pipeline); g_gmax2 reset by csr_kernel (start)
__device__ float g_gmax1[NH] = {-1e30f, -1e30f, -1e30f, -1e30f};
__device__ float g_gmax2 = -1e30f;

// CSR scratch. g_cnt and g_bar zeroed by gat2 at end of each invocation
// (and zero-initialized at load).
__device__ int g_cnt[NN];
__device__ int g_bsum[CSRB];
__device__ int g_rowptr[NN + 1];
__device__ int g_cursor[NN];
__device__ int g_csrc[ETOT];
__device__ int g_bar[3];

__device__ __forceinline__ float lrelu(float v) { return v > 0.0f ? v : NEG_SLOPE * v; }

__device__ __forceinline__ void atomicMaxF(float* addr, float v) {
    int b = __float_as_int(v);
    if (b >= 0) atomicMax((int*)addr, b);
    else        atomicMin((unsigned int*)addr, (unsigned int)b);
}
__device__ __forceinline__ void atomicMaxFShared(int* addr, float v) {
    int b = __float_as_int(v);
    if (b >= 0) atomicMax(addr, b);
    else        atomicMin((unsigned int*)addr, (unsigned int)b);
}

// packed fp32x2 FMA (SASS FFMA2) — only reachable via PTX; 2x fma.rn, bit-exact
__device__ __forceinline__ ull ffma2(ull a, ull b, ull c) {
    ull d;
    asm("fma.rn.f32x2 %0, %1, %2, %3;" : "=l"(d) : "l"(a), "l"(b), "l"(c));
    return d;
}
__device__ __forceinline__ ull fdup(float a) {
    ull r;
    asm("mov.b64 %0, {%1, %1};" : "=l"(r) : "f"(a));
    return r;
}
__device__ __forceinline__ float2 u2f(ull u) {
    float2 f;
    asm("mov.b64 {%0, %1}, %2;" : "=f"(f.x), "=f"(f.y) : "l"(u));
    return f;
}

// grid barrier for the persistent CSR kernel (all CSRB blocks co-resident)
__device__ __forceinline__ void gridbar(int idx) {
    __syncthreads();
    if (threadIdx.x == 0) {
        __threadfence();
        atomicAdd(&g_bar[idx], 1);
        while (((volatile int*)g_bar)[idx] < CSRB) __nanosleep(64);
        __threadfence();
    }
    __syncthreads();
}

// ---------------- persistent CSR build: hist -> scan -> place ----------------
__global__ void __launch_bounds__(256, 4) csr_kernel(const int* __restrict__ src,
                                                     const int* __restrict__ dst) {
    int tid = threadIdx.x;
    int gtid = blockIdx.x * 256 + tid;
    if (blockIdx.x == 0 && tid == 0) g_gmax2 = -1e30f;

    // phase 1: histogram of dst
    for (int e = gtid; e < NE; e += CSRB * 256)
        atomicAdd(&g_cnt[__ldg(dst + e)], 1);
    gridbar(0);

    // phase 2: block-local inclusive scan of (cnt+1), block sums to g_bsum
    __shared__ int s[256];
    __shared__ int wsum[8];
    int i = gtid;
    int val = (i < NN) ? (__ldcg(&g_cnt[i]) + 1) : 0;
    s[tid] = val;
    __syncthreads();
    #pragma unroll
    for (int off = 1; off < 256; off <<= 1) {
        int v = (tid >= off) ? s[tid - off] : 0;
        __syncthreads();
        s[tid] += v;
        __syncthreads();
    }
    int incl = s[tid];
    if (tid == 255) g_bsum[blockIdx.x] = incl;
    gridbar(1);

    // phase 3: cross-block prefix; emit rowptr/cursor/self-loop
    {
        int acc = 0;
        for (int k = tid; k < blockIdx.x; k += 256) acc += __ldcg(&g_bsum[k]);
        int lane = tid & 31;
        #pragma unroll
        for (int o = 16; o >= 1; o >>= 1) acc += __shfl_xor_sync(0xffffffffu, acc, o);
        if (lane == 0) wsum[tid >> 5] = acc;
        __syncthreads();
        int prefix = wsum[0] + wsum[1] + wsum[2] + wsum[3]
                   + wsum[4] + wsum[5] + wsum[6] + wsum[7];
        if (i < NN) {
            int rp = prefix + incl - val;
            g_rowptr[i] = rp;
            g_csrc[rp] = i;          // self loop in slot 0
            g_cursor[i] = rp + 1;
        }
        if (i == NN) g_rowptr[NN] = ETOT;
    }
    gridbar(2);

    // phase 4: place edges
    for (int e = gtid; e < NE; e += CSRB * 256) {
        int dd = __ldg(dst + e);
        int ss = __ldg(src + e);
        int pos = atomicAdd(&g_cursor[dd], 1);
        g_csrc[pos] = ss;
    }
}

// ---------------- GEMM1 (FFMA2, R3 tiling/occupancy) + logits + gmax ----------------
__global__ void gemm1_kernel(const float* __restrict__ A, const float* __restrict__ W,
                             const float* __restrict__ asrc, const float* __restrict__ adst) {
    __shared__ float As[64][132];
    __shared__ int smax[4];
    int tid = threadIdx.x;
    int brow = blockIdx.x * 64;
    if (tid < 4) smax[tid] = 0xFF800000;   // -inf bits
    #pragma unroll
    for (int p = 0; p < 8; p++) {
        int idx = tid + p * 256;
        int m = idx >> 5;
        int k4 = (idx & 31) * 4;
        int gr = brow + m;
        float4 v = (gr < NN) ? *(const float4*)(A + (size_t)gr * FIN + k4)
                             : make_float4(0.f, 0.f, 0.f, 0.f);
        As[m][k4 + 0] = v.x; As[m][k4 + 1] = v.y; As[m][k4 + 2] = v.z; As[m][k4 + 3] = v.w;
    }
    __syncthreads();
    int tx = tid & 15, ty = tid >> 4;
    int c0 = tx * 8, r0 = ty * 4;
    ull acc[4][4];
    #pragma unroll
    for (int j = 0; j < 4; j++)
        #pragma unroll
        for (int c = 0; c < 4; c++) acc[j][c] = 0ULL;
    #pragma unroll 4
    for (int k = 0; k < 128; k++) {
        ulonglong2 wa = __ldg((const ulonglong2*)(W + k * D1 + c0));      // cols c0..c0+3
        ulonglong2 wb = __ldg((const ulonglong2*)(W + k * D1 + c0 + 4));  // cols c0+4..c0+7
        #pragma unroll
        for (int j = 0; j < 4; j++) {
            ull a = fdup(As[r0 + j][k]);
            acc[j][0] = ffma2(a, wa.x, acc[j][0]);
            acc[j][1] = ffma2(a, wa.y, acc[j][1]);
            acc[j][2] = ffma2(a, wb.x, acc[j][2]);
            acc[j][3] = ffma2(a, wb.y, acc[j][3]);
        }
    }
    // unpack, write h1 fp16, stage fp32 tile into smem for logit epilogue
    __syncthreads();
    #pragma unroll
    for (int j = 0; j < 4; j++) {
        float o[8];
        #pragma unroll
        for (int c = 0; c < 4; c++) {
            float2 f = u2f(acc[j][c]);
            o[2 * c] = f.x; o[2 * c + 1] = f.y;
        }
        int row = brow + r0 + j;
        if (row < NN) {
            __half2 p0 = __floats2half2_rn(o[0], o[1]);
            __half2 p1 = __floats2half2_rn(o[2], o[3]);
            __half2 p2 = __floats2half2_rn(o[4], o[5]);
            __half2 p3 = __floats2half2_rn(o[6], o[7]);
            uint4 u = make_uint4(*(unsigned*)&p0, *(unsigned*)&p1,
                                 *(unsigned*)&p2, *(unsigned*)&p3);
            *(uint4*)(g_h1h + (size_t)row * 64 + tx * 4) = u;
        }
        #pragma unroll
        for (int i = 0; i < 8; i++) As[r0 + j][c0 + i] = o[i];
    }
    __syncthreads();
    int wid = tid >> 5, lane = tid & 31;
    int h = lane >> 3;
    int off = (lane & 7) * 4;
    float4 a4 = *(const float4*)(asrc + h * HID + off);
    float4 d4 = *(const float4*)(adst + h * HID + off);
    #pragma unroll
    for (int rr = 0; rr < 8; rr++) {
        int row = wid * 8 + rr;
        int grow = brow + row;
        float4 hv = *(const float4*)(&As[row][lane * 4]);
        float ps = hv.x * a4.x + hv.y * a4.y + hv.z * a4.z + hv.w * a4.w;
        float pd = hv.x * d4.x + hv.y * d4.y + hv.z * d4.z + hv.w * d4.w;
        #pragma unroll
        for (int o = 4; o >= 1; o >>= 1) {
            ps += __shfl_xor_sync(0xffffffffu, ps, o);
            pd += __shfl_xor_sync(0xffffffffu, pd, o);
        }
        if ((lane & 7) == 0 && grow < NN) {
            g_esrc1[grow * 4 + h] = ps;
            g_edst1[grow * 4 + h] = pd;
            atomicMaxFShared(&smax[h], ps);
        }
    }
    __syncthreads();
    if (tid < 4) atomicMaxF(&g_gmax1[tid], __int_as_float(smax[tid]));
}

// ---------------- GAT layer 1: single-pass shifted softmax + fp16 gather ----------------
__global__ void gat1_kernel(const float* __restrict__ bias) {
    int warp = (blockIdx.x * blockDim.x + threadIdx.x) >> 5;
    int lane = threadIdx.x & 31;
    if (warp >= NN) return;
    int d = warp;
    int base = g_rowptr[d];
    int end  = g_rowptr[d + 1];
    int h = lane >> 3;
    float ed_h = g_edst1[d * 4 + h];
    float S = lrelu(g_gmax1[h] + ed_h);   // upper bound of alpha over neighborhood

    float sumA = 0.f, sumB = 0.f;
    float4 accA = make_float4(0.f, 0.f, 0.f, 0.f);
    float4 accB = make_float4(0.f, 0.f, 0.f, 0.f);
    int j = base;
    for (; j + 1 < end; j += 2) {
        int s0 = g_csrc[j];
        int s1 = g_csrc[j + 1];
        float es0 = g_esrc1[s0 * 4 + h];
        float es1 = g_esrc1[s1 * 4 + h];
        uint2 r0 = *(const uint2*)(g_h1h + (size_t)s0 * 64 + lane * 2);
        uint2 r1 = *(const uint2*)(g_h1h + (size_t)s1 * 64 + lane * 2);
        float2 p00 = __half22float2(*(__half2*)&r0.x);
        float2 p01 = __half22float2(*(__half2*)&r0.y);
        float2 p10 = __half22float2(*(__half2*)&r1.x);
        float2 p11 = __half22float2(*(__half2*)&r1.y);
        float w0 = __expf(lrelu(es0 + ed_h) - S);
        float w1 = __expf(lrelu(es1 + ed_h) - S);
        sumA += w0; sumB += w1;
        accA.x += w0 * p00.x; accA.y += w0 * p00.y; accA.z += w0 * p01.x; accA.w += w0 * p01.y;
        accB.x += w1 * p10.x; accB.y += w1 * p10.y; accB.z += w1 * p11.x; accB.w += w1 * p11.y;
    }
    if (j < end) {
        int s0 = g_csrc[j];
        float es0 = g_esrc1[s0 * 4 + h];
        uint2 r0 = *(const uint2*)(g_h1h + (size_t)s0 * 64 + lane * 2);
        float2 p00 = __half22float2(*(__half2*)&r0.x);
        float2 p01 = __half22float2(*(__half2*)&r0.y);
        float w0 = __expf(lrelu(es0 + ed_h) - S);
        sumA += w0;
        accA.x += w0 * p00.x; accA.y += w0 * p00.y; accA.z += w0 * p01.x; accA.w += w0 * p01.y;
    }
    float inv = 1.0f / (sumA + sumB + 1e-16f);
    float4 b = *(const float4*)(bias + lane * 4);
    float4 v;
    v.x = (accA.x + accB.x) * inv + b.x;
    v.y = (accA.y + accB.y) * inv + b.y;
    v.z = (accA.z + accB.z) * inv + b.z;
    v.w = (accA.w + accB.w) * inv + b.w;
    v.x = v.x > 0.f ? v.x : (__expf(v.x) - 1.f);
    v.y = v.y > 0.f ? v.y : (__expf(v.y) - 1.f);
    v.z = v.z > 0.f ? v.z : (__expf(v.z) - 1.f);
    v.w = v.w > 0.f ? v.w : (__expf(v.w) - 1.f);
    *(float4*)(g_agg1 + (size_t)d * D1 + lane * 4) = v;
}

// ---------------- GEMM2 (W in smem, FFMA2) + logits + gmax ----------------
__global__ void gemm2_kernel(const float* __restrict__ W,
                             const float* __restrict__ asrc, const float* __restrict__ adst) {
    __shared__ float As[64][132];
    __shared__ float Ws[128 * NC];
    __shared__ int smax2;
    int tid = threadIdx.x;
    int brow = blockIdx.x * 64;
    if (tid == 0) smax2 = 0xFF800000;
    #pragma unroll
    for (int p = 0; p < 8; p++) {
        int idx = tid + p * 256;
        int m = idx >> 5;
        int k4 = (idx & 31) * 4;
        int gr = brow + m;
        float4 v = (gr < NN) ? *(const float4*)(g_agg1 + (size_t)gr * D1 + k4)
                             : make_float4(0.f, 0.f, 0.f, 0.f);
        As[m][k4 + 0] = v.x; As[m][k4 + 1] = v.y; As[m][k4 + 2] = v.z; As[m][k4 + 3] = v.w;
    }
    #pragma unroll
    for (int p = 0; p < 5; p++) {
        int idx = tid + p * 256;   // 1280 float4 = 5120 floats
        ((float4*)Ws)[idx] = __ldg((const float4*)W + idx);
    }
    __syncthreads();
    int tx = tid & 3, ty = tid >> 2;   // ty = row (0..63), tx = col group (10 cols)
    int c0 = tx * 10;
    ull acc[5] = {0ULL, 0ULL, 0ULL, 0ULL, 0ULL};
    #pragma unroll 4
    for (int k = 0; k < 128; k++) {
        ull a = fdup(As[ty][k]);
        const float* wr = Ws + k * NC + c0;
        #pragma unroll
        for (int i = 0; i < 5; i++)
            acc[i] = ffma2(a, *(const ull*)(wr + 2 * i), acc[i]);
    }
    float o[10];
    #pragma unroll
    for (int i = 0; i < 5; i++) {
        float2 f = u2f(acc[i]);
        o[2 * i] = f.x; o[2 * i + 1] = f.y;
    }
    int grow = brow + ty;
    if (grow < NN) {
        __half2* op = (__half2*)(g_h2h + (size_t)grow * NC + c0);
        #pragma unroll
        for (int i = 0; i < 5; i++) op[i] = __floats2half2_rn(o[2 * i], o[2 * i + 1]);
    }
    __syncthreads();                 // all reads of As/Ws done
    float* Sh = &As[0][0];           // reuse as [64][44]
    #pragma unroll
    for (int i = 0; i < 10; i++) Sh[ty * 44 + c0 + i] = o[i];
    __syncthreads();
    int wid = tid >> 5, lane = tid & 31;
    float a_lo = __ldg(asrc + lane);
    float d_lo = __ldg(adst + lane);
    float a_hi = (lane < 8) ? __ldg(asrc + 32 + lane) : 0.f;
    float d_hi = (lane < 8) ? __ldg(adst + 32 + lane) : 0.f;
    #pragma unroll
    for (int rr = 0; rr < 8; rr++) {
        int row = wid * 8 + rr;
        int gr2 = brow + row;
        float v0 = Sh[row * 44 + lane];
        float v1 = (lane < 8) ? Sh[row * 44 + 32 + lane] : 0.f;
        float ps = v0 * a_lo + v1 * a_hi;
        float pd = v0 * d_lo + v1 * d_hi;
        #pragma unroll
        for (int o2 = 16; o2 >= 1; o2 >>= 1) {
            ps += __shfl_xor_sync(0xffffffffu, ps, o2);
            pd += __shfl_xor_sync(0xffffffffu, pd, o2);
        }
        if (lane == 0 && gr2 < NN) {
            g_esrc2[gr2] = ps;
            g_edst2[gr2] = pd;
            atomicMaxFShared(&smax2, ps);
        }
    }
    __syncthreads();
    if (tid == 0) atomicMaxF(&g_gmax2, __int_as_float(smax2));
}

// ---------------- GAT layer 2: shifted softmax + fp16 gather + log_softmax/softmax ----------------
__global__ void gat2_kernel(const float* __restrict__ bias, float* __restrict__ out) {
    int warp = (blockIdx.x * blockDim.x + threadIdx.x) >> 5;
    int lane = threadIdx.x & 31;
    if (blockIdx.x == 0) {
        if (threadIdx.x < 4) g_gmax1[threadIdx.x] = -1e30f;          // reset for next invocation
        else if (threadIdx.x < 7) g_bar[threadIdx.x - 4] = 0;         // reset grid barriers
    }
    if (warp >= NN) return;
    int d = warp;
    if (lane == 0) g_cnt[d] = 0;   // reset histogram for next invocation
    int base = g_rowptr[d];
    int end  = g_rowptr[d + 1];
    float ed = g_edst2[d];
    float S = lrelu(g_gmax2 + ed);

    float sumA = 0.f, sumB = 0.f;
    float a0A = 0.f, a1A = 0.f, a0B = 0.f, a1B = 0.f;
    int j = base;
    for (; j + 1 < end; j += 2) {
        int s0 = g_csrc[j];
        int s1 = g_csrc[j + 1];
        float es0 = g_esrc2[s0];
        float es1 = g_esrc2[s1];
        const __half* h0 = g_h2h + (size_t)s0 * NC;
        const __half* h1p = g_h2h + (size_t)s1 * NC;
        float f00 = __half2float(h0[lane]);
        float f10 = __half2float(h1p[lane]);
        float f01 = (lane < 8) ? __half2float(h0[32 + lane]) : 0.f;
        float f11 = (lane < 8) ? __half2float(h1p[32 + lane]) : 0.f;
        float w0 = __expf(lrelu(es0 + ed) - S);
        float w1 = __expf(lrelu(es1 + ed) - S);
        sumA += w0; sumB += w1;
        a0A += w0 * f00; a1A += w0 * f01;
        a0B += w1 * f10; a1B += w1 * f11;
    }
    if (j < end) {
        int s0 = g_csrc[j];
        float es0 = g_esrc2[s0];
        const __half* h0 = g_h2h + (size_t)s0 * NC;
        float w0 = __expf(lrelu(es0 + ed) - S);
        sumA += w0;
        a0A += w0 * __half2float(h0[lane]);
        if (lane < 8) a1A += w0 * __half2float(h0[32 + lane]);
    }
    float inv = 1.0f / (sumA + sumB + 1e-16f);
    float acc0 = (a0A + a0B) * inv;
    float acc1 = (a1A + a1B) * inv;

    float v0 = acc0 + __ldg(bias + lane);
    float v1 = (lane < 8) ? (acc1 + __ldg(bias + 32 + lane)) : -INFINITY;
    float m = fmaxf(v0, v1);
    #pragma unroll
    for (int o = 16; o >= 1; o >>= 1) m = fmaxf(m, __shfl_xor_sync(0xffffffffu, m, o));
    float e0 = expf(v0 - m);
    float e1 = (lane < 8) ? expf(v1 - m) : 0.f;
    float sm = e0 + e1;
    #pragma unroll
    for (int o = 16; o >= 1; o >>= 1) sm += __shfl_xor_sync(0xffffffffu, sm, o);
    float ls = logf(sm);
    float invs = 1.0f / sm;
    float* lo = out + (size_t)d * NC;
    float* so = out + (size_t)NN * NC + (size_t)d * NC;
    lo[lane] = v0 - m - ls;
    so[lane] = e0 * invs;
    if (lane < 8) {
        lo[32 + lane] = v1 - m - ls;
        so[32 + lane] = e1 * invs;
    }
}

// ---------------- launch ----------------
extern "C" void kernel_launch(void* const* d_in, const int* in_sizes, int n_in,
                              void* d_out, int out_size) {
    const float* x   = (const float*)d_in[0];
    const int*   ei  = (const int*)d_in[1];
    const float* W1  = (const float*)d_in[2];
    const float* as1 = (const float*)d_in[3];
    const float* ad1 = (const float*)d_in[4];
    const float* b1  = (const float*)d_in[5];
    const float* W2  = (const float*)d_in[6];
    const float* as2 = (const float*)d_in[7];
    const float* ad2 = (const float*)d_in[8];
    const float* b2  = (const float*)d_in[9];
    float* out = (float*)d_out;
    const int* src = ei;
    const int* dst = ei + NE;

    csr_kernel<<<CSRB, 256>>>(src, dst);
    gemm1_kernel<<<782, 256>>>(x, W1, as1, ad1);
    gat1_kernel<<<6250, 256>>>(b1);
    gemm2_kernel<<<782, 256>>>(W2, as2, ad2);
    gat2_kernel<<<6250, 256>>>(b2, out);
}

// round 7
// speedup vs baseline: 1.2894x; 1.2894x over previous
#include <cuda_runtime.h>
#include <cuda_fp16.h>
#include <math.h>

#define NN 50000
#define NE 800000
#define ETOT 850000      // NE + NN self loops
#define FIN 128
#define D1 128           // NH*HID
#define NH 4
#define HID 32
#define NC 40
#define NEG_SLOPE 0.2f
#define CSRB 592         // persistent CSR blocks (4 per SM, all co-resident)

// ---------------- scratch (device globals) ----------------
__device__ __align__(16) __half2 g_h1h[NN * 64];     // x@W1 in fp16 (gather stream)
__device__ __align__(16) float g_esrc1[NN * 4];
__device__ __align__(16) float g_edst1[NN * 4];
__device__ __align__(16) float g_agg1[NN * D1];      // layer1 out fp32 (GEMM2 A)
__device__ __align__(16) __half g_h2h[NN * NC];      // h@W2 in fp16 (gather stream)
__device__ float g_esrc2[NN];
__device__ float g_edst2[NN];
// global max of e_src; reset protocol:
//   g_gmax1 reset by gat2 (end of pipeline); g_gmax2 reset by csr_kernel (start)
__device__ float g_gmax1[NH] = {-1e30f, -1e30f, -1e30f, -1e30f};
__device__ float g_gmax2 = -1e30f;

// CSR scratch. g_cnt and g_bar zeroed by gat2 at end of each invocation
// (and zero-initialized at load).
__device__ int g_cnt[NN];
__device__ int g_bsum[CSRB];
__device__ int g_rowptr[NN + 1];
__device__ int g_cursor[NN];
__device__ int g_csrc[ETOT];
__device__ int g_bar[3];

__device__ __forceinline__ float lrelu(float v) { return v > 0.0f ? v : NEG_SLOPE * v; }

__device__ __forceinline__ void atomicMaxF(float* addr, float v) {
    int b = __float_as_int(v);
    if (b >= 0) atomicMax((int*)addr, b);
    else        atomicMin((unsigned int*)addr, (unsigned int)b);
}
__device__ __forceinline__ void atomicMaxFShared(int* addr, float v) {
    int b = __float_as_int(v);
    if (b >= 0) atomicMax(addr, b);
    else        atomicMin((unsigned int*)addr, (unsigned int)b);
}

// fp32 -> tf32 (round-to-nearest-even on 10-bit mantissa, kept in 32-bit reg)
__device__ __forceinline__ unsigned tf32c(float f) {
    unsigned u;
    asm("cvt.rna.tf32.f32 %0, %1;" : "=r"(u) : "f"(f));
    return u;
}

// m16n8k8 tf32 MMA, row-major A, col-major B, fp32 accumulate
__device__ __forceinline__ void mma_tf32(float* c, const unsigned* a, unsigned b0, unsigned b1) {
    asm volatile(
        "mma.sync.aligned.m16n8k8.row.col.f32.tf32.tf32.f32 "
        "{%0,%1,%2,%3}, {%4,%5,%6,%7}, {%8,%9}, {%0,%1,%2,%3};"
        : "+f"(c[0]), "+f"(c[1]), "+f"(c[2]), "+f"(c[3])
        : "r"(a[0]), "r"(a[1]), "r"(a[2]), "r"(a[3]), "r"(b0), "r"(b1));
}

// grid barrier for the persistent CSR kernel (all CSRB blocks co-resident)
__device__ __forceinline__ void gridbar(int idx) {
    __syncthreads();
    if (threadIdx.x == 0) {
        __threadfence();
        atomicAdd(&g_bar[idx], 1);
        while (((volatile int*)g_bar)[idx] < CSRB) __nanosleep(64);
        __threadfence();
    }
    __syncthreads();
}

// ---------------- persistent CSR build: hist -> scan -> place ----------------
__global__ void __launch_bounds__(256, 4) csr_kernel(const int* __restrict__ src,
                                                     const int* __restrict__ dst) {
    int tid = threadIdx.x;
    int gtid = blockIdx.x * 256 + tid;
    if (blockIdx.x == 0 && tid == 0) g_gmax2 = -1e30f;

    // phase 1: histogram of dst
    for (int e = gtid; e < NE; e += CSRB * 256)
        atomicAdd(&g_cnt[__ldg(dst + e)], 1);
    gridbar(0);

    // phase 2: block-local inclusive scan of (cnt+1), block sums to g_bsum
    __shared__ int s[256];
    __shared__ int wsum[8];
    int i = gtid;
    int val = (i < NN) ? (__ldcg(&g_cnt[i]) + 1) : 0;
    s[tid] = val;
    __syncthreads();
    #pragma unroll
    for (int off = 1; off < 256; off <<= 1) {
        int v = (tid >= off) ? s[tid - off] : 0;
        __syncthreads();
        s[tid] += v;
        __syncthreads();
    }
    int incl = s[tid];
    if (tid == 255) g_bsum[blockIdx.x] = incl;
    gridbar(1);

    // phase 3: cross-block prefix; emit rowptr/cursor/self-loop
    {
        int acc = 0;
        for (int k = tid; k < blockIdx.x; k += 256) acc += __ldcg(&g_bsum[k]);
        int lane = tid & 31;
        #pragma unroll
        for (int o = 16; o >= 1; o >>= 1) acc += __shfl_xor_sync(0xffffffffu, acc, o);
        if (lane == 0) wsum[tid >> 5] = acc;
        __syncthreads();
        int prefix = wsum[0] + wsum[1] + wsum[2] + wsum[3]
                   + wsum[4] + wsum[5] + wsum[6] + wsum[7];
        if (i < NN) {
            int rp = prefix + incl - val;
            g_rowptr[i] = rp;
            g_csrc[rp] = i;          // self loop in slot 0
            g_cursor[i] = rp + 1;
        }
        if (i == NN) g_rowptr[NN] = ETOT;
    }
    gridbar(2);

    // phase 4: place edges
    for (int e = gtid; e < NE; e += CSRB * 256) {
        int dd = __ldg(dst + e);
        int ss = __ldg(src + e);
        int pos = atomicAdd(&g_cursor[dd], 1);
        g_csrc[pos] = ss;
    }
}

// ---------------- GEMM1 (tf32 mma.sync) + logits + gmax ----------------
// dyn smem: As[64][132] tf32 + Wt[128][132] tf32 (n-major) = 101376 B
#define G1_SMEM ((64 * 132 + 128 * 132) * 4)
__global__ void __launch_bounds__(256, 2) gemm1_kernel(
        const float* __restrict__ A, const float* __restrict__ W,
        const float* __restrict__ asrc, const float* __restrict__ adst) {
    extern __shared__ unsigned sm1[];
    unsigned* As = sm1;                 // [64][132]
    unsigned* Wt = sm1 + 64 * 132;      // [128 n][132 k]
    __shared__ int smax[4];
    int tid = threadIdx.x;
    int brow = blockIdx.x * 64;
    if (tid < 4) smax[tid] = 0xFF800000;   // -inf bits
    // stage A tile (tf32)
    #pragma unroll
    for (int p = 0; p < 8; p++) {
        int idx = tid + p * 256;
        int m = idx >> 5;
        int k4 = (idx & 31) * 4;
        int gr = brow + m;
        float4 v = (gr < NN) ? *(const float4*)(A + (size_t)gr * FIN + k4)
                             : make_float4(0.f, 0.f, 0.f, 0.f);
        unsigned* pp = As + m * 132 + k4;
        pp[0] = tf32c(v.x); pp[1] = tf32c(v.y); pp[2] = tf32c(v.z); pp[3] = tf32c(v.w);
    }
    // stage W transposed (tf32): Wt[n][k]
    #pragma unroll
    for (int p = 0; p < 16; p++) {
        int idx = tid + p * 256;        // 4096 float4 groups
        int k = idx >> 5;
        int n4 = (idx & 31) * 4;
        float4 w = __ldg((const float4*)(W + k * D1 + n4));
        Wt[(n4 + 0) * 132 + k] = tf32c(w.x);
        Wt[(n4 + 1) * 132 + k] = tf32c(w.y);
        Wt[(n4 + 2) * 132 + k] = tf32c(w.z);
        Wt[(n4 + 3) * 132 + k] = tf32c(w.w);
    }
    __syncthreads();
    int wid = tid >> 5, lane = tid & 31;
    int wm = wid & 1, wn = wid >> 1;        // 2 M-groups x 4 N-groups of 32
    int g = lane >> 2, t = lane & 3;
    float c[2][4][4];
    #pragma unroll
    for (int mi = 0; mi < 2; mi++)
        #pragma unroll
        for (int ni = 0; ni < 4; ni++)
            #pragma unroll
            for (int q = 0; q < 4; q++) c[mi][ni][q] = 0.f;
    #pragma unroll
    for (int k0 = 0; k0 < 128; k0 += 8) {
        unsigned a[2][4];
        #pragma unroll
        for (int mi = 0; mi < 2; mi++) {
            const unsigned* ap = As + (wm * 32 + mi * 16 + g) * 132 + k0 + t;
            a[mi][0] = ap[0];
            a[mi][1] = ap[8 * 132];
            a[mi][2] = ap[4];
            a[mi][3] = ap[8 * 132 + 4];
        }
        unsigned b[4][2];
        #pragma unroll
        for (int ni = 0; ni < 4; ni++) {
            const unsigned* bp = Wt + (wn * 32 + ni * 8 + g) * 132 + k0 + t;
            b[ni][0] = bp[0];
            b[ni][1] = bp[4];
        }
        #pragma unroll
        for (int mi = 0; mi < 2; mi++)
            #pragma unroll
            for (int ni = 0; ni < 4; ni++)
                mma_tf32(c[mi][ni], a[mi], b[ni][0], b[ni][1]);
    }
    // stage C into smem [64][132]
    __syncthreads();
    float* Sh = (float*)sm1;
    #pragma unroll
    for (int mi = 0; mi < 2; mi++)
        #pragma unroll
        for (int ni = 0; ni < 4; ni++) {
            int r = wm * 32 + mi * 16 + g;
            int col = wn * 32 + ni * 8 + 2 * t;
            Sh[r * 132 + col]           = c[mi][ni][0];
            Sh[r * 132 + col + 1]       = c[mi][ni][1];
            Sh[(r + 8) * 132 + col]     = c[mi][ni][2];
            Sh[(r + 8) * 132 + col + 1] = c[mi][ni][3];
        }
    __syncthreads();
    // fp16 h1 write
    #pragma unroll
    for (int p = 0; p < 8; p++) {
        int task = tid + p * 256;       // 2048 tasks: 64 rows x 32 col-groups(4)
        int row = task >> 5;
        int c4 = (task & 31) * 4;
        int grow = brow + row;
        if (grow < NN) {
            float4 f = *(const float4*)&Sh[row * 132 + c4];
            __half2 h0 = __floats2half2_rn(f.x, f.y);
            __half2 h1 = __floats2half2_rn(f.z, f.w);
            uint2 u = make_uint2(*(unsigned*)&h0, *(unsigned*)&h1);
            *(uint2*)(g_h1h + (size_t)grow * 64 + (task & 31) * 2) = u;
        }
    }
    // attention logits + gmax
    int h = lane >> 3;
    int off = (lane & 7) * 4;
    float4 a4 = *(const float4*)(asrc + h * HID + off);
    float4 d4 = *(const float4*)(adst + h * HID + off);
    #pragma unroll
    for (int rr = 0; rr < 8; rr++) {
        int row = wid * 8 + rr;
        int grow = brow + row;
        float4 hv = *(const float4*)&Sh[row * 132 + lane * 4];
        float ps = hv.x * a4.x + hv.y * a4.y + hv.z * a4.z + hv.w * a4.w;
        float pd = hv.x * d4.x + hv.y * d4.y + hv.z * d4.z + hv.w * d4.w;
        #pragma unroll
        for (int o = 4; o >= 1; o >>= 1) {
            ps += __shfl_xor_sync(0xffffffffu, ps, o);
            pd += __shfl_xor_sync(0xffffffffu, pd, o);
        }
        if ((lane & 7) == 0 && grow < NN) {
            g_esrc1[grow * 4 + h] = ps;
            g_edst1[grow * 4 + h] = pd;
            atomicMaxFShared(&smax[h], ps);
        }
    }
    __syncthreads();
    if (tid < 4) atomicMaxF(&g_gmax1[tid], __int_as_float(smax[tid]));
}

// ---------------- GAT layer 1: single-pass shifted softmax + fp16 gather ----------------
__global__ void gat1_kernel(const float* __restrict__ bias) {
    int warp = (blockIdx.x * blockDim.x + threadIdx.x) >> 5;
    int lane = threadIdx.x & 31;
    if (warp >= NN) return;
    int d = warp;
    int base = g_rowptr[d];
    int end  = g_rowptr[d + 1];
    int h = lane >> 3;
    float ed_h = g_edst1[d * 4 + h];
    float S = lrelu(g_gmax1[h] + ed_h);   // upper bound of alpha over neighborhood

    float sumA = 0.f, sumB = 0.f;
    float4 accA = make_float4(0.f, 0.f, 0.f, 0.f);
    float4 accB = make_float4(0.f, 0.f, 0.f, 0.f);
    int j = base;
    for (; j + 1 < end; j += 2) {
        int s0 = g_csrc[j];
        int s1 = g_csrc[j + 1];
        float es0 = g_esrc1[s0 * 4 + h];
        float es1 = g_esrc1[s1 * 4 + h];
        uint2 r0 = *(const uint2*)(g_h1h + (size_t)s0 * 64 + lane * 2);
        uint2 r1 = *(const uint2*)(g_h1h + (size_t)s1 * 64 + lane * 2);
        float2 p00 = __half22float2(*(__half2*)&r0.x);
        float2 p01 = __half22float2(*(__half2*)&r0.y);
        float2 p10 = __half22float2(*(__half2*)&r1.x);
        float2 p11 = __half22float2(*(__half2*)&r1.y);
        float w0 = __expf(lrelu(es0 + ed_h) - S);
        float w1 = __expf(lrelu(es1 + ed_h) - S);
        sumA += w0; sumB += w1;
        accA.x += w0 * p00.x; accA.y += w0 * p00.y; accA.z += w0 * p01.x; accA.w += w0 * p01.y;
        accB.x += w1 * p10.x; accB.y += w1 * p10.y; accB.z += w1 * p11.x; accB.w += w1 * p11.y;
    }
    if (j < end) {
        int s0 = g_csrc[j];
        float es0 = g_esrc1[s0 * 4 + h];
        uint2 r0 = *(const uint2*)(g_h1h + (size_t)s0 * 64 + lane * 2);
        float2 p00 = __half22float2(*(__half2*)&r0.x);
        float2 p01 = __half22float2(*(__half2*)&r0.y);
        float w0 = __expf(lrelu(es0 + ed_h) - S);
        sumA += w0;
        accA.x += w0 * p00.x; accA.y += w0 * p00.y; accA.z += w0 * p01.x; accA.w += w0 * p01.y;
    }
    float inv = 1.0f / (sumA + sumB + 1e-16f);
    float4 b = *(const float4*)(bias + lane * 4);
    float4 v;
    v.x = (accA.x + accB.x) * inv + b.x;
    v.y = (accA.y + accB.y) * inv + b.y;
    v.z = (accA.z + accB.z) * inv + b.z;
    v.w = (accA.w + accB.w) * inv + b.w;
    v.x = v.x > 0.f ? v.x : (__expf(v.x) - 1.f);
    v.y = v.y > 0.f ? v.y : (__expf(v.y) - 1.f);
    v.z = v.z > 0.f ? v.z : (__expf(v.z) - 1.f);
    v.w = v.w > 0.f ? v.w : (__expf(v.w) - 1.f);
    *(float4*)(g_agg1 + (size_t)d * D1 + lane * 4) = v;
}

// ---------------- GEMM2 (tf32 mma.sync) + logits + gmax ----------------
// dyn smem: As[128][132] + Wt[40][132] = 88704 B
#define G2_SMEM ((128 * 132 + 40 * 132) * 4)
__global__ void __launch_bounds__(256, 2) gemm2_kernel(
        const float* __restrict__ W,
        const float* __restrict__ asrc, const float* __restrict__ adst) {
    extern __shared__ unsigned sm2[];
    unsigned* As = sm2;                  // [128][132]
    unsigned* Wt = sm2 + 128 * 132;      // [40 n][132 k]
    __shared__ int smax2;
    int tid = threadIdx.x;
    int brow = blockIdx.x * 128;
    if (tid == 0) smax2 = 0xFF800000;
    // stage A tile (g_agg1, tf32)
    #pragma unroll
    for (int p = 0; p < 16; p++) {
        int idx = tid + p * 256;        // 4096 float4 groups
        int m = idx >> 5;
        int k4 = (idx & 31) * 4;
        int gr = brow + m;
        float4 v = (gr < NN) ? *(const float4*)(g_agg1 + (size_t)gr * D1 + k4)
                             : make_float4(0.f, 0.f, 0.f, 0.f);
        unsigned* pp = As + m * 132 + k4;
        pp[0] = tf32c(v.x); pp[1] = tf32c(v.y); pp[2] = tf32c(v.z); pp[3] = tf32c(v.w);
    }
    // stage W2 transposed (tf32): Wt[n][k], W2 is [128][40]
    #pragma unroll
    for (int p = 0; p < 5; p++) {
        int idx = tid + p * 256;        // 1280 float4 groups
        int k = idx / 10;
        int n4 = (idx % 10) * 4;
        float4 w = __ldg((const float4*)(W + k * NC + n4));
        Wt[(n4 + 0) * 132 + k] = tf32c(w.x);
        Wt[(n4 + 1) * 132 + k] = tf32c(w.y);
        Wt[(n4 + 2) * 132 + k] = tf32c(w.z);
        Wt[(n4 + 3) * 132 + k] = tf32c(w.w);
    }
    __syncthreads();
    int wid = tid >> 5, lane = tid & 31;
    int g = lane >> 2, t = lane & 3;
    float c[5][4];
    #pragma unroll
    for (int ni = 0; ni < 5; ni++)
        #pragma unroll
        for (int q = 0; q < 4; q++) c[ni][q] = 0.f;
    #pragma unroll
    for (int k0 = 0; k0 < 128; k0 += 8) {
        unsigned a[4];
        const unsigned* ap = As + (wid * 16 + g) * 132 + k0 + t;
        a[0] = ap[0];
        a[1] = ap[8 * 132];
        a[2] = ap[4];
        a[3] = ap[8 * 132 + 4];
        #pragma unroll
        for (int ni = 0; ni < 5; ni++) {
            const unsigned* bp = Wt + (ni * 8 + g) * 132 + k0 + t;
            mma_tf32(c[ni], a, bp[0], bp[4]);
        }
    }
    // stage C into smem [128][44]
    __syncthreads();
    float* Sh = (float*)sm2;
    #pragma unroll
    for (int ni = 0; ni < 5; ni++) {
        int r = wid * 16 + g;
        int col = ni * 8 + 2 * t;
        Sh[r * 44 + col]           = c[ni][0];
        Sh[r * 44 + col + 1]       = c[ni][1];
        Sh[(r + 8) * 44 + col]     = c[ni][2];
        Sh[(r + 8) * 44 + col + 1] = c[ni][3];
    }
    __syncthreads();
    // fp16 h2 write: 2 threads per row, 20 cols each
    {
        int row = tid >> 1;
        int half = tid & 1;
        int grow = brow + row;
        if (grow < NN) {
            const float* sp = &Sh[row * 44 + half * 20];
            uint2* op = (uint2*)(g_h2h + (size_t)grow * NC + half * 20);
            #pragma unroll
            for (int i = 0; i < 5; i++) {
                __half2 h0 = __floats2half2_rn(sp[4 * i],     sp[4 * i + 1]);
                __half2 h1 = __floats2half2_rn(sp[4 * i + 2], sp[4 * i + 3]);
                op[i] = make_uint2(*(unsigned*)&h0, *(unsigned*)&h1);
            }
        }
    }
    // attention logits + gmax: each warp handles 16 rows
    float a_lo = __ldg(asrc + lane);
    float d_lo = __ldg(adst + lane);
    float a_hi = (lane < 8) ? __ldg(asrc + 32 + lane) : 0.f;
    float d_hi = (lane < 8) ? __ldg(adst + 32 + lane) : 0.f;
    #pragma unroll
    for (int rr = 0; rr < 16; rr++) {
        int row = wid * 16 + rr;
        int grow = brow + row;
        float v0 = Sh[row * 44 + lane];
        float v1 = (lane < 8) ? Sh[row * 44 + 32 + lane] : 0.f;
        float ps = v0 * a_lo + v1 * a_hi;
        float pd = v0 * d_lo + v1 * d_hi;
        #pragma unroll
        for (int o = 16; o >= 1; o >>= 1) {
            ps += __shfl_xor_sync(0xffffffffu, ps, o);
            pd += __shfl_xor_sync(0xffffffffu, pd, o);
        }
        if (lane == 0 && grow < NN) {
            g_esrc2[grow] = ps;
            g_edst2[grow] = pd;
            atomicMaxFShared(&smax2, ps);
        }
    }
    __syncthreads();
    if (tid == 0) atomicMaxF(&g_gmax2, __int_as_float(smax2));
}

// ---------------- GAT layer 2: shifted softmax + fp16 gather + log_softmax/softmax ----------------
__global__ void gat2_kernel(const float* __restrict__ bias, float* __restrict__ out) {
    int warp = (blockIdx.x * blockDim.x + threadIdx.x) >> 5;
    int lane = threadIdx.x & 31;
    if (blockIdx.x == 0) {
        if (threadIdx.x < 4) g_gmax1[threadIdx.x] = -1e30f;          // reset for next invocation
        else if (threadIdx.x < 7) g_bar[threadIdx.x - 4] = 0;         // reset grid barriers
    }
    if (warp >= NN) return;
    int d = warp;
    if (lane == 0) g_cnt[d] = 0;   // reset histogram for next invocation
    int base = g_rowptr[d];
    int end  = g_rowptr[d + 1];
    float ed = g_edst2[d];
    float S = lrelu(g_gmax2 + ed);

    float sumA = 0.f, sumB = 0.f;
    float a0A = 0.f, a1A = 0.f, a0B = 0.f, a1B = 0.f;
    int j = base;
    for (; j + 1 < end; j += 2) {
        int s0 = g_csrc[j];
        int s1 = g_csrc[j + 1];
        float es0 = g_esrc2[s0];
        float es1 = g_esrc2[s1];
        const __half* h0 = g_h2h + (size_t)s0 * NC;
        const __half* h1p = g_h2h + (size_t)s1 * NC;
        float f00 = __half2float(h0[lane]);
        float f10 = __half2float(h1p[lane]);
        float f01 = (lane < 8) ? __half2float(h0[32 + lane]) : 0.f;
        float f11 = (lane < 8) ? __half2float(h1p[32 + lane]) : 0.f;
        float w0 = __expf(lrelu(es0 + ed) - S);
        float w1 = __expf(lrelu(es1 + ed) - S);
        sumA += w0; sumB += w1;
        a0A += w0 * f00; a1A += w0 * f01;
        a0B += w1 * f10; a1B += w1 * f11;
    }
    if (j < end) {
        int s0 = g_csrc[j];
        float es0 = g_esrc2[s0];
        const __half* h0 = g_h2h + (size_t)s0 * NC;
        float w0 = __expf(lrelu(es0 + ed) - S);
        sumA += w0;
        a0A += w0 * __half2float(h0[lane]);
        if (lane < 8) a1A += w0 * __half2float(h0[32 + lane]);
    }
    float inv = 1.0f / (sumA + sumB + 1e-16f);
    float acc0 = (a0A + a0B) * inv;
    float acc1 = (a1A + a1B) * inv;

    float v0 = acc0 + __ldg(bias + lane);
    float v1 = (lane < 8) ? (acc1 + __ldg(bias + 32 + lane)) : -INFINITY;
    float m = fmaxf(v0, v1);
    #pragma unroll
    for (int o = 16; o >= 1; o >>= 1) m = fmaxf(m, __shfl_xor_sync(0xffffffffu, m, o));
    float e0 = expf(v0 - m);
    float e1 = (lane < 8) ? expf(v1 - m) : 0.f;
    float sm = e0 + e1;
    #pragma unroll
    for (int o = 16; o >= 1; o >>= 1) sm += __shfl_xor_sync(0xffffffffu, sm, o);
    float ls = logf(sm);
    float invs = 1.0f / sm;
    float* lo = out + (size_t)d * NC;
    float* so = out + (size_t)NN * NC + (size_t)d * NC;
    lo[lane] = v0 - m - ls;
    so[lane] = e0 * invs;
    if (lane < 8) {
        lo[32 + lane] = v1 - m - ls;
        so[32 + lane] = e1 * invs;
    }
}

// ---------------- launch ----------------
extern "C" void kernel_launch(void* const* d_in, const int* in_sizes, int n_in,
                              void* d_out, int out_size) {
    const float* x   = (const float*)d_in[0];
    const int*   ei  = (const int*)d_in[1];
    const float* W1  = (const float*)d_in[2];
    const float* as1 = (const float*)d_in[3];
    const float* ad1 = (const float*)d_in[4];
    const float* b1  = (const float*)d_in[5];
    const float* W2  = (const float*)d_in[6];
    const float* as2 = (const float*)d_in[7];
    const float* ad2 = (const float*)d_in[8];
    const float* b2  = (const float*)d_in[9];
    float* out = (float*)d_out;
    const int* src = ei;
    const int* dst = ei + NE;

    cudaFuncSetAttribute(gemm1_kernel, cudaFuncAttributeMaxDynamicSharedMemorySize, G1_SMEM);
    cudaFuncSetAttribute(gemm2_kernel, cudaFuncAttributeMaxDynamicSharedMemorySize, G2_SMEM);

    csr_kernel<<<CSRB, 256>>>(src, dst);
    gemm1_kernel<<<782, 256, G1_SMEM>>>(x, W1, as1, ad1);
    gat1_kernel<<<6250, 256>>>(b1);
    gemm2_kernel<<<391, 256, G2_SMEM>>>(W2, as2, ad2);
    gat2_kernel<<<6250, 256>>>(b2, out);
}

// round 8
// speedup vs baseline: 1.3962x; 1.0828x over previous
#include <cuda_runtime.h>
#include <cuda_fp16.h>
#include <math.h>

#define NN 50000
#define NE 800000
#define ETOT 850000      // NE + NN self loops
#define FIN 128
#define D1 128           // NH*HID
#define NH 4
#define HID 32
#define NC 40
#define NEG_SLOPE 0.2f
#define CSRB 592         // persistent CSR blocks (4 per SM, all co-resident)

// ---------------- scratch (device globals) ----------------
__device__ __align__(16) __half2 g_h1h[NN * 64];     // x@W1 in fp16 (gather stream)
__device__ __align__(16) float g_esrc1[NN * 4];
__device__ __align__(16) float g_edst1[NN * 4];
__device__ __align__(16) __half g_agg1h[NN * D1];    // layer1 out in fp16 (GEMM2 A)
__device__ __align__(16) __half g_h2h[NN * NC];      // h@W2 in fp16 (gather stream)
__device__ float g_esrc2[NN];
__device__ float g_edst2[NN];
// global max of e_src; reset protocol:
//   g_gmax1 reset by gat2 (end of pipeline); g_gmax2 reset by csr_kernel (start)
__device__ float g_gmax1[NH] = {-1e30f, -1e30f, -1e30f, -1e30f};
__device__ float g_gmax2 = -1e30f;

// CSR scratch. g_cnt and g_bar zeroed by gat2 at end of each invocation
// (and zero-initialized at load).
__device__ int g_cnt[NN];
__device__ int g_bsum[CSRB];
__device__ int g_rowptr[NN + 1];
__device__ int g_cursor[NN];
__device__ int g_csrc[ETOT];
__device__ int g_bar[3];

__device__ __forceinline__ float lrelu(float v) { return v > 0.0f ? v : NEG_SLOPE * v; }

__device__ __forceinline__ void atomicMaxF(float* addr, float v) {
    int b = __float_as_int(v);
    if (b >= 0) atomicMax((int*)addr, b);
    else        atomicMin((unsigned int*)addr, (unsigned int)b);
}
__device__ __forceinline__ void atomicMaxFShared(int* addr, float v) {
    int b = __float_as_int(v);
    if (b >= 0) atomicMax(addr, b);
    else        atomicMin((unsigned int*)addr, (unsigned int)b);
}

// m16n8k16 fp16 MMA, row-major A, col-major B, fp32 accumulate
__device__ __forceinline__ void mma_f16(float* c, const unsigned* a, unsigned b0, unsigned b1) {
    asm volatile(
        "mma.sync.aligned.m16n8k16.row.col.f32.f16.f16.f32 "
        "{%0,%1,%2,%3}, {%4,%5,%6,%7}, {%8,%9}, {%0,%1,%2,%3};"
        : "+f"(c[0]), "+f"(c[1]), "+f"(c[2]), "+f"(c[3])
        : "r"(a[0]), "r"(a[1]), "r"(a[2]), "r"(a[3]), "r"(b0), "r"(b1));
}

// grid barrier for the persistent CSR kernel (all CSRB blocks co-resident)
__device__ __forceinline__ void gridbar(int idx) {
    __syncthreads();
    if (threadIdx.x == 0) {
        __threadfence();
        atomicAdd(&g_bar[idx], 1);
        while (((volatile int*)g_bar)[idx] < CSRB) __nanosleep(64);
        __threadfence();
    }
    __syncthreads();
}

// ---------------- persistent CSR build: hist -> scan -> place ----------------
__global__ void __launch_bounds__(256, 4) csr_kernel(const int* __restrict__ src,
                                                     const int* __restrict__ dst) {
    int tid = threadIdx.x;
    int gtid = blockIdx.x * 256 + tid;
    if (blockIdx.x == 0 && tid == 0) g_gmax2 = -1e30f;

    // phase 1: histogram of dst
    for (int e = gtid; e < NE; e += CSRB * 256)
        atomicAdd(&g_cnt[__ldg(dst + e)], 1);
    gridbar(0);

    // phase 2: block-local inclusive scan of (cnt+1), block sums to g_bsum
    __shared__ int s[256];
    __shared__ int wsum[8];
    int i = gtid;
    int val = (i < NN) ? (__ldcg(&g_cnt[i]) + 1) : 0;
    s[tid] = val;
    __syncthreads();
    #pragma unroll
    for (int off = 1; off < 256; off <<= 1) {
        int v = (tid >= off) ? s[tid - off] : 0;
        __syncthreads();
        s[tid] += v;
        __syncthreads();
    }
    int incl = s[tid];
    if (tid == 255) g_bsum[blockIdx.x] = incl;
    gridbar(1);

    // phase 3: cross-block prefix; emit rowptr/cursor/self-loop
    {
        int acc = 0;
        for (int k = tid; k < blockIdx.x; k += 256) acc += __ldcg(&g_bsum[k]);
        int lane = tid & 31;
        #pragma unroll
        for (int o = 16; o >= 1; o >>= 1) acc += __shfl_xor_sync(0xffffffffu, acc, o);
        if (lane == 0) wsum[tid >> 5] = acc;
        __syncthreads();
        int prefix = wsum[0] + wsum[1] + wsum[2] + wsum[3]
                   + wsum[4] + wsum[5] + wsum[6] + wsum[7];
        if (i < NN) {
            int rp = prefix + incl - val;
            g_rowptr[i] = rp;
            g_csrc[rp] = i;          // self loop in slot 0
            g_cursor[i] = rp + 1;
        }
        if (i == NN) g_rowptr[NN] = ETOT;
    }
    gridbar(2);

    // phase 4: place edges
    for (int e = gtid; e < NE; e += CSRB * 256) {
        int dd = __ldg(dst + e);
        int ss = __ldg(src + e);
        int pos = atomicAdd(&g_cursor[dd], 1);
        g_csrc[pos] = ss;
    }
}

// ---------------- GEMM1 (fp16 mma m16n8k16) + logits + gmax ----------------
// dyn smem: Ah[64][136] half + Wth[128][136] half = 52224 B
#define G1_SMEM ((64 * 136 + 128 * 136) * 2)
__global__ void __launch_bounds__(256, 3) gemm1_kernel(
        const float* __restrict__ A, const float* __restrict__ W,
        const float* __restrict__ asrc, const float* __restrict__ adst) {
    extern __shared__ __half sm1h[];
    __half* Ah  = sm1h;               // [64][136]
    __half* Wth = sm1h + 64 * 136;    // [128 n][136 k]
    __shared__ int smax[4];
    int tid = threadIdx.x;
    int brow = blockIdx.x * 64;
    if (tid < 4) smax[tid] = 0xFF800000;   // -inf bits
    // stage A tile as fp16
    #pragma unroll
    for (int p = 0; p < 8; p++) {
        int idx = tid + p * 256;
        int m = idx >> 5;
        int k4 = (idx & 31) * 4;
        int gr = brow + m;
        float4 v = (gr < NN) ? *(const float4*)(A + (size_t)gr * FIN + k4)
                             : make_float4(0.f, 0.f, 0.f, 0.f);
        __half2 h0 = __floats2half2_rn(v.x, v.y);
        __half2 h1 = __floats2half2_rn(v.z, v.w);
        *(uint2*)(Ah + m * 136 + k4) = make_uint2(*(unsigned*)&h0, *(unsigned*)&h1);
    }
    // stage W transposed as fp16: Wth[n][k]
    #pragma unroll
    for (int p = 0; p < 16; p++) {
        int idx = tid + p * 256;        // 4096 float4 groups
        int k = idx >> 5;
        int n4 = (idx & 31) * 4;
        float4 w = __ldg((const float4*)(W + k * D1 + n4));
        Wth[(n4 + 0) * 136 + k] = __float2half(w.x);
        Wth[(n4 + 1) * 136 + k] = __float2half(w.y);
        Wth[(n4 + 2) * 136 + k] = __float2half(w.z);
        Wth[(n4 + 3) * 136 + k] = __float2half(w.w);
    }
    __syncthreads();
    int wid = tid >> 5, lane = tid & 31;
    int wm = wid & 1, wn = wid >> 1;        // 2 M-groups x 4 N-groups of 32
    int g = lane >> 2, t = lane & 3;
    float c[2][4][4];
    #pragma unroll
    for (int mi = 0; mi < 2; mi++)
        #pragma unroll
        for (int ni = 0; ni < 4; ni++)
            #pragma unroll
            for (int q = 0; q < 4; q++) c[mi][ni][q] = 0.f;
    #pragma unroll
    for (int k0 = 0; k0 < 128; k0 += 16) {
        unsigned a[2][4];
        #pragma unroll
        for (int mi = 0; mi < 2; mi++) {
            const __half* ap = Ah + (wm * 32 + mi * 16 + g) * 136 + k0 + 2 * t;
            a[mi][0] = *(const unsigned*)(ap);
            a[mi][1] = *(const unsigned*)(ap + 8 * 136);
            a[mi][2] = *(const unsigned*)(ap + 8);
            a[mi][3] = *(const unsigned*)(ap + 8 * 136 + 8);
        }
        unsigned b[4][2];
        #pragma unroll
        for (int ni = 0; ni < 4; ni++) {
            const __half* bp = Wth + (wn * 32 + ni * 8 + g) * 136 + k0 + 2 * t;
            b[ni][0] = *(const unsigned*)(bp);
            b[ni][1] = *(const unsigned*)(bp + 8);
        }
        #pragma unroll
        for (int mi = 0; mi < 2; mi++)
            #pragma unroll
            for (int ni = 0; ni < 4; ni++)
                mma_f16(c[mi][ni], a[mi], b[ni][0], b[ni][1]);
    }
    // stage C (fp32) into smem [64][132]
    __syncthreads();
    float* Sh = (float*)sm1h;
    #pragma unroll
    for (int mi = 0; mi < 2; mi++)
        #pragma unroll
        for (int ni = 0; ni < 4; ni++) {
            int r = wm * 32 + mi * 16 + g;
            int col = wn * 32 + ni * 8 + 2 * t;
            Sh[r * 132 + col]           = c[mi][ni][0];
            Sh[r * 132 + col + 1]       = c[mi][ni][1];
            Sh[(r + 8) * 132 + col]     = c[mi][ni][2];
            Sh[(r + 8) * 132 + col + 1] = c[mi][ni][3];
        }
    __syncthreads();
    // fp16 h1 write
    #pragma unroll
    for (int p = 0; p < 8; p++) {
        int task = tid + p * 256;       // 2048 tasks: 64 rows x 32 col-groups(4)
        int row = task >> 5;
        int c4 = (task & 31) * 4;
        int grow = brow + row;
        if (grow < NN) {
            float4 f = *(const float4*)&Sh[row * 132 + c4];
            __half2 h0 = __floats2half2_rn(f.x, f.y);
            __half2 h1 = __floats2half2_rn(f.z, f.w);
            uint2 u = make_uint2(*(unsigned*)&h0, *(unsigned*)&h1);
            *(uint2*)(g_h1h + (size_t)grow * 64 + (task & 31) * 2) = u;
        }
    }
    // attention logits + gmax
    int h = lane >> 3;
    int off = (lane & 7) * 4;
    float4 a4 = *(const float4*)(asrc + h * HID + off);
    float4 d4 = *(const float4*)(adst + h * HID + off);
    #pragma unroll
    for (int rr = 0; rr < 8; rr++) {
        int row = wid * 8 + rr;
        int grow = brow + row;
        float4 hv = *(const float4*)&Sh[row * 132 + lane * 4];
        float ps = hv.x * a4.x + hv.y * a4.y + hv.z * a4.z + hv.w * a4.w;
        float pd = hv.x * d4.x + hv.y * d4.y + hv.z * d4.z + hv.w * d4.w;
        #pragma unroll
        for (int o = 4; o >= 1; o >>= 1) {
            ps += __shfl_xor_sync(0xffffffffu, ps, o);
            pd += __shfl_xor_sync(0xffffffffu, pd, o);
        }
        if ((lane & 7) == 0 && grow < NN) {
            g_esrc1[grow * 4 + h] = ps;
            g_edst1[grow * 4 + h] = pd;
            atomicMaxFShared(&smax[h], ps);
        }
    }
    __syncthreads();
    if (tid < 4) atomicMaxF(&g_gmax1[tid], __int_as_float(smax[tid]));
}

// ---------------- GAT layer 1: single-pass shifted softmax + fp16 gather ----------------
__global__ void gat1_kernel(const float* __restrict__ bias) {
    int warp = (blockIdx.x * blockDim.x + threadIdx.x) >> 5;
    int lane = threadIdx.x & 31;
    if (warp >= NN) return;
    int d = warp;
    int base = g_rowptr[d];
    int end  = g_rowptr[d + 1];
    int h = lane >> 3;
    float ed_h = g_edst1[d * 4 + h];
    float S = lrelu(g_gmax1[h] + ed_h);   // upper bound of alpha over neighborhood

    float sumA = 0.f, sumB = 0.f;
    float4 accA = make_float4(0.f, 0.f, 0.f, 0.f);
    float4 accB = make_float4(0.f, 0.f, 0.f, 0.f);
    int j = base;
    for (; j + 1 < end; j += 2) {
        int s0 = g_csrc[j];
        int s1 = g_csrc[j + 1];
        float es0 = g_esrc1[s0 * 4 + h];
        float es1 = g_esrc1[s1 * 4 + h];
        uint2 r0 = *(const uint2*)(g_h1h + (size_t)s0 * 64 + lane * 2);
        uint2 r1 = *(const uint2*)(g_h1h + (size_t)s1 * 64 + lane * 2);
        float2 p00 = __half22float2(*(__half2*)&r0.x);
        float2 p01 = __half22float2(*(__half2*)&r0.y);
        float2 p10 = __half22float2(*(__half2*)&r1.x);
        float2 p11 = __half22float2(*(__half2*)&r1.y);
        float w0 = __expf(lrelu(es0 + ed_h) - S);
        float w1 = __expf(lrelu(es1 + ed_h) - S);
        sumA += w0; sumB += w1;
        accA.x += w0 * p00.x; accA.y += w0 * p00.y; accA.z += w0 * p01.x; accA.w += w0 * p01.y;
        accB.x += w1 * p10.x; accB.y += w1 * p10.y; accB.z += w1 * p11.x; accB.w += w1 * p11.y;
    }
    if (j < end) {
        int s0 = g_csrc[j];
        float es0 = g_esrc1[s0 * 4 + h];
        uint2 r0 = *(const uint2*)(g_h1h + (size_t)s0 * 64 + lane * 2);
        float2 p00 = __half22float2(*(__half2*)&r0.x);
        float2 p01 = __half22float2(*(__half2*)&r0.y);
        float w0 = __expf(lrelu(es0 + ed_h) - S);
        sumA += w0;
        accA.x += w0 * p00.x; accA.y += w0 * p00.y; accA.z += w0 * p01.x; accA.w += w0 * p01.y;
    }
    float inv = 1.0f / (sumA + sumB + 1e-16f);
    float4 b = *(const float4*)(bias + lane * 4);
    float4 v;
    v.x = (accA.x + accB.x) * inv + b.x;
    v.y = (accA.y + accB.y) * inv + b.y;
    v.z = (accA.z + accB.z) * inv + b.z;
    v.w = (accA.w + accB.w) * inv + b.w;
    v.x = v.x > 0.f ? v.x : (__expf(v.x) - 1.f);
    v.y = v.y > 0.f ? v.y : (__expf(v.y) - 1.f);
    v.z = v.z > 0.f ? v.z : (__expf(v.z) - 1.f);
    v.w = v.w > 0.f ? v.w : (__expf(v.w) - 1.f);
    // store fp16 directly (GEMM2 consumes fp16)
    __half2 o0 = __floats2half2_rn(v.x, v.y);
    __half2 o1 = __floats2half2_rn(v.z, v.w);
    *(uint2*)(g_agg1h + (size_t)d * D1 + lane * 4) = make_uint2(*(unsigned*)&o0, *(unsigned*)&o1);
}

// ---------------- GEMM2 (fp16 mma m16n8k16) + logits + gmax ----------------
// dyn smem: Ah[128][136] + Wth[40][136] halves = 45696 B
#define G2_SMEM ((128 * 136 + 40 * 136) * 2)
__global__ void __launch_bounds__(256, 3) gemm2_kernel(
        const float* __restrict__ W,
        const float* __restrict__ asrc, const float* __restrict__ adst) {
    extern __shared__ __half sm2h[];
    __half* Ah  = sm2h;                // [128][136]
    __half* Wth = sm2h + 128 * 136;    // [40 n][136 k]
    __shared__ int smax2;
    int tid = threadIdx.x;
    int brow = blockIdx.x * 128;
    if (tid == 0) smax2 = 0xFF800000;
    // stage A tile (already fp16): pure uint4 copies, 8 per thread
    #pragma unroll
    for (int p = 0; p < 8; p++) {
        int idx = tid + p * 256;        // 2048 uint4 = 128 rows x 16 groups
        int m = idx >> 4;
        int h8 = (idx & 15) * 8;
        int gr = brow + m;
        uint4 v = (gr < NN) ? *(const uint4*)(g_agg1h + (size_t)gr * D1 + h8)
                            : make_uint4(0u, 0u, 0u, 0u);
        *(uint4*)(Ah + m * 136 + h8) = v;
    }
    // stage W2 transposed as fp16: Wth[n][k], W2 is [128][40]
    #pragma unroll
    for (int p = 0; p < 5; p++) {
        int idx = tid + p * 256;        // 1280 float4 groups
        int k = idx / 10;
        int n4 = (idx % 10) * 4;
        float4 w = __ldg((const float4*)(W + k * NC + n4));
        Wth[(n4 + 0) * 136 + k] = __float2half(w.x);
        Wth[(n4 + 1) * 136 + k] = __float2half(w.y);
        Wth[(n4 + 2) * 136 + k] = __float2half(w.z);
        Wth[(n4 + 3) * 136 + k] = __float2half(w.w);
    }
    __syncthreads();
    int wid = tid >> 5, lane = tid & 31;
    int g = lane >> 2, t = lane & 3;
    float c[5][4];
    #pragma unroll
    for (int ni = 0; ni < 5; ni++)
        #pragma unroll
        for (int q = 0; q < 4; q++) c[ni][q] = 0.f;
    #pragma unroll
    for (int k0 = 0; k0 < 128; k0 += 16) {
        unsigned a[4];
        const __half* ap = Ah + (wid * 16 + g) * 136 + k0 + 2 * t;
        a[0] = *(const unsigned*)(ap);
        a[1] = *(const unsigned*)(ap + 8 * 136);
        a[2] = *(const unsigned*)(ap + 8);
        a[3] = *(const unsigned*)(ap + 8 * 136 + 8);
        #pragma unroll
        for (int ni = 0; ni < 5; ni++) {
            const __half* bp = Wth + (ni * 8 + g) * 136 + k0 + 2 * t;
            mma_f16(c[ni], a, *(const unsigned*)(bp), *(const unsigned*)(bp + 8));
        }
    }
    // stage C into smem [128][44]
    __syncthreads();
    float* Sh = (float*)sm2h;
    #pragma unroll
    for (int ni = 0; ni < 5; ni++) {
        int r = wid * 16 + g;
        int col = ni * 8 + 2 * t;
        Sh[r * 44 + col]           = c[ni][0];
        Sh[r * 44 + col + 1]       = c[ni][1];
        Sh[(r + 8) * 44 + col]     = c[ni][2];
        Sh[(r + 8) * 44 + col + 1] = c[ni][3];
    }
    __syncthreads();
    // fp16 h2 write: 2 threads per row, 20 cols each
    {
        int row = tid >> 1;
        int half = tid & 1;
        int grow = brow + row;
        if (grow < NN) {
            const float* sp = &Sh[row * 44 + half * 20];
            uint2* op = (uint2*)(g_h2h + (size_t)grow * NC + half * 20);
            #pragma unroll
            for (int i = 0; i < 5; i++) {
                __half2 h0 = __floats2half2_rn(sp[4 * i],     sp[4 * i + 1]);
                __half2 h1 = __floats2half2_rn(sp[4 * i + 2], sp[4 * i + 3]);
                op[i] = make_uint2(*(unsigned*)&h0, *(unsigned*)&h1);
            }
        }
    }
    // attention logits + gmax: each warp handles 16 rows
    float a_lo = __ldg(asrc + lane);
    float d_lo = __ldg(adst + lane);
    float a_hi = (lane < 8) ? __ldg(asrc + 32 + lane) : 0.f;
    float d_hi = (lane < 8) ? __ldg(adst + 32 + lane) : 0.f;
    #pragma unroll
    for (int rr = 0; rr < 16; rr++) {
        int row = wid * 16 + rr;
        int grow = brow + row;
        float v0 = Sh[row * 44 + lane];
        float v1 = (lane < 8) ? Sh[row * 44 + 32 + lane] : 0.f;
        float ps = v0 * a_lo + v1 * a_hi;
        float pd = v0 * d_lo + v1 * d_hi;
        #pragma unroll
        for (int o = 16; o >= 1; o >>= 1) {
            ps += __shfl_xor_sync(0xffffffffu, ps, o);
            pd += __shfl_xor_sync(0xffffffffu, pd, o);
        }
        if (lane == 0 && grow < NN) {
            g_esrc2[grow] = ps;
            g_edst2[grow] = pd;
            atomicMaxFShared(&smax2, ps);
        }
    }
    __syncthreads();
    if (tid == 0) atomicMaxF(&g_gmax2, __int_as_float(smax2));
}

// ---------------- GAT layer 2: shifted softmax + fp16 gather + log_softmax/softmax ----------------
__global__ void gat2_kernel(const float* __restrict__ bias, float* __restrict__ out) {
    int warp = (blockIdx.x * blockDim.x + threadIdx.x) >> 5;
    int lane = threadIdx.x & 31;
    if (blockIdx.x == 0) {
        if (threadIdx.x < 4) g_gmax1[threadIdx.x] = -1e30f;          // reset for next invocation
        else if (threadIdx.x < 7) g_bar[threadIdx.x - 4] = 0;         // reset grid barriers
    }
    if (warp >= NN) return;
    int d = warp;
    if (lane == 0) g_cnt[d] = 0;   // reset histogram for next invocation
    int base = g_rowptr[d];
    int end  = g_rowptr[d + 1];
    float ed = g_edst2[d];
    float S = lrelu(g_gmax2 + ed);

    float sumA = 0.f, sumB = 0.f;
    float a0A = 0.f, a1A = 0.f, a0B = 0.f, a1B = 0.f;
    int j = base;
    for (; j + 1 < end; j += 2) {
        int s0 = g_csrc[j];
        int s1 = g_csrc[j + 1];
        float es0 = g_esrc2[s0];
        float es1 = g_esrc2[s1];
        const __half* h0 = g_h2h + (size_t)s0 * NC;
        const __half* h1p = g_h2h + (size_t)s1 * NC;
        float f00 = __half2float(h0[lane]);
        float f10 = __half2float(h1p[lane]);
        float f01 = (lane < 8) ? __half2float(h0[32 + lane]) : 0.f;
        float f11 = (lane < 8) ? __half2float(h1p[32 + lane]) : 0.f;
        float w0 = __expf(lrelu(es0 + ed) - S);
        float w1 = __expf(lrelu(es1 + ed) - S);
        sumA += w0; sumB += w1;
        a0A += w0 * f00; a1A += w0 * f01;
        a0B += w1 * f10; a1B += w1 * f11;
    }
    if (j < end) {
        int s0 = g_csrc[j];
        float es0 = g_esrc2[s0];
        const __half* h0 = g_h2h + (size_t)s0 * NC;
        float w0 = __expf(lrelu(es0 + ed) - S);
        sumA += w0;
        a0A += w0 * __half2float(h0[lane]);
        if (lane < 8) a1A += w0 * __half2float(h0[32 + lane]);
    }
    float inv = 1.0f / (sumA + sumB + 1e-16f);
    float acc0 = (a0A + a0B) * inv;
    float acc1 = (a1A + a1B) * inv;

    float v0 = acc0 + __ldg(bias + lane);
    float v1 = (lane < 8) ? (acc1 + __ldg(bias + 32 + lane)) : -INFINITY;
    float m = fmaxf(v0, v1);
    #pragma unroll
    for (int o = 16; o >= 1; o >>= 1) m = fmaxf(m, __shfl_xor_sync(0xffffffffu, m, o));
    float e0 = expf(v0 - m);
    float e1 = (lane < 8) ? expf(v1 - m) : 0.f;
    float sm = e0 + e1;
    #pragma unroll
    for (int o = 16; o >= 1; o >>= 1) sm += __shfl_xor_sync(0xffffffffu, sm, o);
    float ls = logf(sm);
    float invs = 1.0f / sm;
    float* lo = out + (size_t)d * NC;
    float* so = out + (size_t)NN * NC + (size_t)d * NC;
    lo[lane] = v0 - m - ls;
    so[lane] = e0 * invs;
    if (lane < 8) {
        lo[32 + lane] = v1 - m - ls;
        so[32 + lane] = e1 * invs;
    }
}

// ---------------- launch ----------------
extern "C" void kernel_launch(void* const* d_in, const int* in_sizes, int n_in,
                              void* d_out, int out_size) {
    const float* x   = (const float*)d_in[0];
    const int*   ei  = (const int*)d_in[1];
    const float* W1  = (const float*)d_in[2];
    const float* as1 = (const float*)d_in[3];
    const float* ad1 = (const float*)d_in[4];
    const float* b1  = (const float*)d_in[5];
    const float* W2  = (const float*)d_in[6];
    const float* as2 = (const float*)d_in[7];
    const float* ad2 = (const float*)d_in[8];
    const float* b2  = (const float*)d_in[9];
    float* out = (float*)d_out;
    const int* src = ei;
    const int* dst = ei + NE;

    cudaFuncSetAttribute(gemm1_kernel, cudaFuncAttributeMaxDynamicSharedMemorySize, G1_SMEM);
    cudaFuncSetAttribute(gemm2_kernel, cudaFuncAttributeMaxDynamicSharedMemorySize, G2_SMEM);

    csr_kernel<<<CSRB, 256>>>(src, dst);
    gemm1_kernel<<<782, 256, G1_SMEM>>>(x, W1, as1, ad1);
    gat1_kernel<<<6250, 256>>>(b1);
    gemm2_kernel<<<391, 256, G2_SMEM>>>(W2, as2, ad2);
    gat2_kernel<<<6250, 256>>>(b2, out);
}

// round 9
// speedup vs baseline: 1.5277x; 1.0942x over previous
#include <cuda_runtime.h>
#include <cuda_fp16.h>
#include <math.h>

#define NN 50000
#define NE 800000
#define ETOT 850000      // NE + NN self loops
#define FIN 128
#define D1 128           // NH*HID
#define NH 4
#define HID 32
#define NC 40
#define NEG_SLOPE 0.2f
#define CSRB 296         // CSR blocks inside fused kernel (all wave-1 co-resident)
#define G1B 782          // gemm1 tile blocks

// ---------------- scratch (device globals) ----------------
__device__ __align__(16) __half2 g_h1h[NN * 64];     // x@W1 in fp16 (gather stream)
__device__ __align__(16) float g_esrc1[NN * 4];
__device__ __align__(16) float g_edst1[NN * 4];
__device__ __align__(16) __half g_agg1h[NN * D1];    // layer1 out in fp16 (GEMM2 A)
__device__ __align__(16) __half g_h2h[NN * NC];      // h@W2 in fp16 (gather stream)
__device__ float g_esrc2[NN];
__device__ float g_edst2[NN];
// global max of e_src; reset protocol:
//   g_gmax1 reset by gat2 (end of pipeline); g_gmax2 reset by fused kernel (start)
__device__ float g_gmax1[NH] = {-1e30f, -1e30f, -1e30f, -1e30f};
__device__ float g_gmax2 = -1e30f;

// CSR scratch. g_cnt and g_bar zeroed by gat2 at end of each invocation
// (and zero-initialized at load).
__device__ int g_cnt[NN];
__device__ int g_bsum[CSRB];
__device__ int g_rowptr[NN + 1];
__device__ int g_cursor[NN];
__device__ int g_csrc[ETOT];
__device__ int g_bar[3];

__device__ __forceinline__ float lrelu(float v) { return v > 0.0f ? v : NEG_SLOPE * v; }

__device__ __forceinline__ void atomicMaxF(float* addr, float v) {
    int b = __float_as_int(v);
    if (b >= 0) atomicMax((int*)addr, b);
    else        atomicMin((unsigned int*)addr, (unsigned int)b);
}
__device__ __forceinline__ void atomicMaxFShared(int* addr, float v) {
    int b = __float_as_int(v);
    if (b >= 0) atomicMax(addr, b);
    else        atomicMin((unsigned int*)addr, (unsigned int)b);
}

// m16n8k16 fp16 MMA, row-major A, col-major B, fp32 accumulate
__device__ __forceinline__ void mma_f16(float* c, const unsigned* a, unsigned b0, unsigned b1) {
    asm volatile(
        "mma.sync.aligned.m16n8k16.row.col.f32.f16.f16.f32 "
        "{%0,%1,%2,%3}, {%4,%5,%6,%7}, {%8,%9}, {%0,%1,%2,%3};"
        : "+f"(c[0]), "+f"(c[1]), "+f"(c[2]), "+f"(c[3])
        : "r"(a[0]), "r"(a[1]), "r"(a[2]), "r"(a[3]), "r"(b0), "r"(b1));
}

// grid barrier among the CSRB csr blocks of the fused kernel
__device__ __forceinline__ void gridbar(int idx) {
    __syncthreads();
    if (threadIdx.x == 0) {
        __threadfence();
        atomicAdd(&g_bar[idx], 1);
        while (((volatile int*)g_bar)[idx] < CSRB) __nanosleep(64);
        __threadfence();
    }
    __syncthreads();
}

// ---------------- fused kernel: CSR build (blocks 0..CSRB-1) || GEMM1 (rest) ----------------
// dyn smem: Ah[64][136] half + Wth[128][136] half = 52224 B (gemm1); csr uses a slice
#define G1_SMEM ((64 * 136 + 128 * 136) * 2)
__global__ void __launch_bounds__(256, 3) fused1_kernel(
        const int* __restrict__ src, const int* __restrict__ dst,
        const float* __restrict__ A, const float* __restrict__ W,
        const float* __restrict__ asrc, const float* __restrict__ adst) {
    extern __shared__ char smraw[];
    int tid = threadIdx.x;

    if (blockIdx.x < CSRB) {
        // ================= CSR build =================
        int* s = (int*)smraw;            // [256]
        __shared__ int wsum[8];
        int gtid = blockIdx.x * 256 + tid;
        if (blockIdx.x == 0 && tid == 0) g_gmax2 = -1e30f;

        // phase 1: histogram of dst
        for (int e = gtid; e < NE; e += CSRB * 256)
            atomicAdd(&g_cnt[__ldg(dst + e)], 1);
        gridbar(0);

        // phase 2: block-local inclusive scan of (cnt+1), block totals
        int i = gtid;
        int val = (i < NN) ? (__ldcg(&g_cnt[i]) + 1) : 0;
        s[tid] = val;
        __syncthreads();
        #pragma unroll
        for (int off = 1; off < 256; off <<= 1) {
            int v = (tid >= off) ? s[tid - off] : 0;
            __syncthreads();
            s[tid] += v;
            __syncthreads();
        }
        int incl = s[tid];
        if (tid == 255) g_bsum[blockIdx.x] = incl;
        gridbar(1);

        // phase 3: cross-block prefix; emit rowptr/cursor/self-loop
        {
            int acc = 0;
            for (int k = tid; k < blockIdx.x; k += 256) acc += __ldcg(&g_bsum[k]);
            int lane = tid & 31;
            #pragma unroll
            for (int o = 16; o >= 1; o >>= 1) acc += __shfl_xor_sync(0xffffffffu, acc, o);
            if (lane == 0) wsum[tid >> 5] = acc;
            __syncthreads();
            int prefix = wsum[0] + wsum[1] + wsum[2] + wsum[3]
                       + wsum[4] + wsum[5] + wsum[6] + wsum[7];
            if (i < NN) {
                int rp = prefix + incl - val;
                g_rowptr[i] = rp;
                g_csrc[rp] = i;          // self loop in slot 0
                g_cursor[i] = rp + 1;
            }
            if (i == NN) g_rowptr[NN] = ETOT;
        }
        gridbar(2);

        // phase 4: place edges
        for (int e = gtid; e < NE; e += CSRB * 256) {
            int dd = __ldg(dst + e);
            int ss = __ldg(src + e);
            int pos = atomicAdd(&g_cursor[dd], 1);
            g_csrc[pos] = ss;
        }
        return;
    }

    // ================= GEMM1 (fp16 mma) + logits + gmax =================
    __half* Ah  = (__half*)smraw;          // [64][136]
    __half* Wth = (__half*)smraw + 64 * 136;  // [128 n][136 k]
    __shared__ int smax[4];
    int brow = (blockIdx.x - CSRB) * 64;
    if (tid < 4) smax[tid] = 0xFF800000;   // -inf bits
    // stage A tile as fp16
    #pragma unroll
    for (int p = 0; p < 8; p++) {
        int idx = tid + p * 256;
        int m = idx >> 5;
        int k4 = (idx & 31) * 4;
        int gr = brow + m;
        float4 v = (gr < NN) ? *(const float4*)(A + (size_t)gr * FIN + k4)
                             : make_float4(0.f, 0.f, 0.f, 0.f);
        __half2 h0 = __floats2half2_rn(v.x, v.y);
        __half2 h1 = __floats2half2_rn(v.z, v.w);
        *(uint2*)(Ah + m * 136 + k4) = make_uint2(*(unsigned*)&h0, *(unsigned*)&h1);
    }
    // stage W transposed as fp16: Wth[n][k]
    #pragma unroll
    for (int p = 0; p < 16; p++) {
        int idx = tid + p * 256;        // 4096 float4 groups
        int k = idx >> 5;
        int n4 = (idx & 31) * 4;
        float4 w = __ldg((const float4*)(W + k * D1 + n4));
        Wth[(n4 + 0) * 136 + k] = __float2half(w.x);
        Wth[(n4 + 1) * 136 + k] = __float2half(w.y);
        Wth[(n4 + 2) * 136 + k] = __float2half(w.z);
        Wth[(n4 + 3) * 136 + k] = __float2half(w.w);
    }
    __syncthreads();
    int wid = tid >> 5, lane = tid & 31;
    int wm = wid & 1, wn = wid >> 1;        // 2 M-groups x 4 N-groups of 32
    int g = lane >> 2, t = lane & 3;
    float c[2][4][4];
    #pragma unroll
    for (int mi = 0; mi < 2; mi++)
        #pragma unroll
        for (int ni = 0; ni < 4; ni++)
            #pragma unroll
            for (int q = 0; q < 4; q++) c[mi][ni][q] = 0.f;
    #pragma unroll
    for (int k0 = 0; k0 < 128; k0 += 16) {
        unsigned a[2][4];
        #pragma unroll
        for (int mi = 0; mi < 2; mi++) {
            const __half* ap = Ah + (wm * 32 + mi * 16 + g) * 136 + k0 + 2 * t;
            a[mi][0] = *(const unsigned*)(ap);
            a[mi][1] = *(const unsigned*)(ap + 8 * 136);
            a[mi][2] = *(const unsigned*)(ap + 8);
            a[mi][3] = *(const unsigned*)(ap + 8 * 136 + 8);
        }
        unsigned b[4][2];
        #pragma unroll
        for (int ni = 0; ni < 4; ni++) {
            const __half* bp = Wth + (wn * 32 + ni * 8 + g) * 136 + k0 + 2 * t;
            b[ni][0] = *(const unsigned*)(bp);
            b[ni][1] = *(const unsigned*)(bp + 8);
        }
        #pragma unroll
        for (int mi = 0; mi < 2; mi++)
            #pragma unroll
            for (int ni = 0; ni < 4; ni++)
                mma_f16(c[mi][ni], a[mi], b[ni][0], b[ni][1]);
    }
    // stage C (fp32) into smem [64][132]
    __syncthreads();
    float* Sh = (float*)smraw;
    #pragma unroll
    for (int mi = 0; mi < 2; mi++)
        #pragma unroll
        for (int ni = 0; ni < 4; ni++) {
            int r = wm * 32 + mi * 16 + g;
            int col = wn * 32 + ni * 8 + 2 * t;
            Sh[r * 132 + col]           = c[mi][ni][0];
            Sh[r * 132 + col + 1]       = c[mi][ni][1];
            Sh[(r + 8) * 132 + col]     = c[mi][ni][2];
            Sh[(r + 8) * 132 + col + 1] = c[mi][ni][3];
        }
    __syncthreads();
    // fp16 h1 write
    #pragma unroll
    for (int p = 0; p < 8; p++) {
        int task = tid + p * 256;       // 2048 tasks: 64 rows x 32 col-groups(4)
        int row = task >> 5;
        int c4 = (task & 31) * 4;
        int grow = brow + row;
        if (grow < NN) {
            float4 f = *(const float4*)&Sh[row * 132 + c4];
            __half2 h0 = __floats2half2_rn(f.x, f.y);
            __half2 h1 = __floats2half2_rn(f.z, f.w);
            uint2 u = make_uint2(*(unsigned*)&h0, *(unsigned*)&h1);
            *(uint2*)(g_h1h + (size_t)grow * 64 + (task & 31) * 2) = u;
        }
    }
    // attention logits + gmax
    int h = lane >> 3;
    int off = (lane & 7) * 4;
    float4 a4 = *(const float4*)(asrc + h * HID + off);
    float4 d4 = *(const float4*)(adst + h * HID + off);
    #pragma unroll
    for (int rr = 0; rr < 8; rr++) {
        int row = wid * 8 + rr;
        int grow = brow + row;
        float4 hv = *(const float4*)&Sh[row * 132 + lane * 4];
        float ps = hv.x * a4.x + hv.y * a4.y + hv.z * a4.z + hv.w * a4.w;
        float pd = hv.x * d4.x + hv.y * d4.y + hv.z * d4.z + hv.w * d4.w;
        #pragma unroll
        for (int o = 4; o >= 1; o >>= 1) {
            ps += __shfl_xor_sync(0xffffffffu, ps, o);
            pd += __shfl_xor_sync(0xffffffffu, pd, o);
        }
        if ((lane & 7) == 0 && grow < NN) {
            g_esrc1[grow * 4 + h] = ps;
            g_edst1[grow * 4 + h] = pd;
            atomicMaxFShared(&smax[h], ps);
        }
    }
    __syncthreads();
    if (tid < 4) atomicMaxF(&g_gmax1[tid], __int_as_float(smax[tid]));
}

// ---------------- GAT layer 1: shifted softmax + fp16 gather (x4 MLP) ----------------
__global__ void gat1_kernel(const float* __restrict__ bias) {
    int warp = (blockIdx.x * blockDim.x + threadIdx.x) >> 5;
    int lane = threadIdx.x & 31;
    if (warp >= NN) return;
    int d = warp;
    int base = g_rowptr[d];
    int end  = g_rowptr[d + 1];
    int h = lane >> 3;
    float ed_h = g_edst1[d * 4 + h];
    float S = lrelu(g_gmax1[h] + ed_h);   // upper bound of alpha over neighborhood

    float sumA = 0.f, sumB = 0.f;
    float4 accA = make_float4(0.f, 0.f, 0.f, 0.f);
    float4 accB = make_float4(0.f, 0.f, 0.f, 0.f);
    int j = base;
    for (; j + 3 < end; j += 4) {
        int s0 = g_csrc[j];
        int s1 = g_csrc[j + 1];
        int s2 = g_csrc[j + 2];
        int s3 = g_csrc[j + 3];
        float es0 = g_esrc1[s0 * 4 + h];
        float es1 = g_esrc1[s1 * 4 + h];
        float es2 = g_esrc1[s2 * 4 + h];
        float es3 = g_esrc1[s3 * 4 + h];
        uint2 r0 = *(const uint2*)(g_h1h + (size_t)s0 * 64 + lane * 2);
        uint2 r1 = *(const uint2*)(g_h1h + (size_t)s1 * 64 + lane * 2);
        uint2 r2 = *(const uint2*)(g_h1h + (size_t)s2 * 64 + lane * 2);
        uint2 r3 = *(const uint2*)(g_h1h + (size_t)s3 * 64 + lane * 2);
        float w0 = __expf(lrelu(es0 + ed_h) - S);
        float w1 = __expf(lrelu(es1 + ed_h) - S);
        float w2 = __expf(lrelu(es2 + ed_h) - S);
        float w3 = __expf(lrelu(es3 + ed_h) - S);
        sumA += w0 + w2; sumB += w1 + w3;
        float2 p;
        p = __half22float2(*(__half2*)&r0.x); accA.x += w0 * p.x; accA.y += w0 * p.y;
        p = __half22float2(*(__half2*)&r0.y); accA.z += w0 * p.x; accA.w += w0 * p.y;
        p = __half22float2(*(__half2*)&r1.x); accB.x += w1 * p.x; accB.y += w1 * p.y;
        p = __half22float2(*(__half2*)&r1.y); accB.z += w1 * p.x; accB.w += w1 * p.y;
        p = __half22float2(*(__half2*)&r2.x); accA.x += w2 * p.x; accA.y += w2 * p.y;
        p = __half22float2(*(__half2*)&r2.y); accA.z += w2 * p.x; accA.w += w2 * p.y;
        p = __half22float2(*(__half2*)&r3.x); accB.x += w3 * p.x; accB.y += w3 * p.y;
        p = __half22float2(*(__half2*)&r3.y); accB.z += w3 * p.x; accB.w += w3 * p.y;
    }
    for (; j < end; j++) {
        int s0 = g_csrc[j];
        float es0 = g_esrc1[s0 * 4 + h];
        uint2 r0 = *(const uint2*)(g_h1h + (size_t)s0 * 64 + lane * 2);
        float w0 = __expf(lrelu(es0 + ed_h) - S);
        sumA += w0;
        float2 p;
        p = __half22float2(*(__half2*)&r0.x); accA.x += w0 * p.x; accA.y += w0 * p.y;
        p = __half22float2(*(__half2*)&r0.y); accA.z += w0 * p.x; accA.w += w0 * p.y;
    }
    float inv = 1.0f / (sumA + sumB + 1e-16f);
    float4 b = *(const float4*)(bias + lane * 4);
    float4 v;
    v.x = (accA.x + accB.x) * inv + b.x;
    v.y = (accA.y + accB.y) * inv + b.y;
    v.z = (accA.z + accB.z) * inv + b.z;
    v.w = (accA.w + accB.w) * inv + b.w;
    v.x = v.x > 0.f ? v.x : (__expf(v.x) - 1.f);
    v.y = v.y > 0.f ? v.y : (__expf(v.y) - 1.f);
    v.z = v.z > 0.f ? v.z : (__expf(v.z) - 1.f);
    v.w = v.w > 0.f ? v.w : (__expf(v.w) - 1.f);
    // store fp16 directly (GEMM2 consumes fp16)
    __half2 o0 = __floats2half2_rn(v.x, v.y);
    __half2 o1 = __floats2half2_rn(v.z, v.w);
    *(uint2*)(g_agg1h + (size_t)d * D1 + lane * 4) = make_uint2(*(unsigned*)&o0, *(unsigned*)&o1);
}

// ---------------- GEMM2 (fp16 mma m16n8k16) + logits + gmax ----------------
// dyn smem: Ah[128][136] + Wth[40][136] halves = 45696 B
#define G2_SMEM ((128 * 136 + 40 * 136) * 2)
__global__ void __launch_bounds__(256, 3) gemm2_kernel(
        const float* __restrict__ W,
        const float* __restrict__ asrc, const float* __restrict__ adst) {
    extern __shared__ __half sm2h[];
    __half* Ah  = sm2h;                // [128][136]
    __half* Wth = sm2h + 128 * 136;    // [40 n][136 k]
    __shared__ int smax2;
    int tid = threadIdx.x;
    int brow = blockIdx.x * 128;
    if (tid == 0) smax2 = 0xFF800000;
    // stage A tile (already fp16): pure uint4 copies, 8 per thread
    #pragma unroll
    for (int p = 0; p < 8; p++) {
        int idx = tid + p * 256;        // 2048 uint4 = 128 rows x 16 groups
        int m = idx >> 4;
        int h8 = (idx & 15) * 8;
        int gr = brow + m;
        uint4 v = (gr < NN) ? *(const uint4*)(g_agg1h + (size_t)gr * D1 + h8)
                            : make_uint4(0u, 0u, 0u, 0u);
        *(uint4*)(Ah + m * 136 + h8) = v;
    }
    // stage W2 transposed as fp16: Wth[n][k], W2 is [128][40]
    #pragma unroll
    for (int p = 0; p < 5; p++) {
        int idx = tid + p * 256;        // 1280 float4 groups
        int k = idx / 10;
        int n4 = (idx % 10) * 4;
        float4 w = __ldg((const float4*)(W + k * NC + n4));
        Wth[(n4 + 0) * 136 + k] = __float2half(w.x);
        Wth[(n4 + 1) * 136 + k] = __float2half(w.y);
        Wth[(n4 + 2) * 136 + k] = __float2half(w.z);
        Wth[(n4 + 3) * 136 + k] = __float2half(w.w);
    }
    __syncthreads();
    int wid = tid >> 5, lane = tid & 31;
    int g = lane >> 2, t = lane & 3;
    float c[5][4];
    #pragma unroll
    for (int ni = 0; ni < 5; ni++)
        #pragma unroll
        for (int q = 0; q < 4; q++) c[ni][q] = 0.f;
    #pragma unroll
    for (int k0 = 0; k0 < 128; k0 += 16) {
        unsigned a[4];
        const __half* ap = Ah + (wid * 16 + g) * 136 + k0 + 2 * t;
        a[0] = *(const unsigned*)(ap);
        a[1] = *(const unsigned*)(ap + 8 * 136);
        a[2] = *(const unsigned*)(ap + 8);
        a[3] = *(const unsigned*)(ap + 8 * 136 + 8);
        #pragma unroll
        for (int ni = 0; ni < 5; ni++) {
            const __half* bp = Wth + (ni * 8 + g) * 136 + k0 + 2 * t;
            mma_f16(c[ni], a, *(const unsigned*)(bp), *(const unsigned*)(bp + 8));
        }
    }
    // stage C into smem [128][44]
    __syncthreads();
    float* Sh = (float*)sm2h;
    #pragma unroll
    for (int ni = 0; ni < 5; ni++) {
        int r = wid * 16 + g;
        int col = ni * 8 + 2 * t;
        Sh[r * 44 + col]           = c[ni][0];
        Sh[r * 44 + col + 1]       = c[ni][1];
        Sh[(r + 8) * 44 + col]     = c[ni][2];
        Sh[(r + 8) * 44 + col + 1] = c[ni][3];
    }
    __syncthreads();
    // fp16 h2 write: 2 threads per row, 20 cols each
    {
        int row = tid >> 1;
        int half = tid & 1;
        int grow = brow + row;
        if (grow < NN) {
            const float* sp = &Sh[row * 44 + half * 20];
            uint2* op = (uint2*)(g_h2h + (size_t)grow * NC + half * 20);
            #pragma unroll
            for (int i = 0; i < 5; i++) {
                __half2 h0 = __floats2half2_rn(sp[4 * i],     sp[4 * i + 1]);
                __half2 h1 = __floats2half2_rn(sp[4 * i + 2], sp[4 * i + 3]);
                op[i] = make_uint2(*(unsigned*)&h0, *(unsigned*)&h1);
            }
        }
    }
    // attention logits + gmax: each warp handles 16 rows
    float a_lo = __ldg(asrc + lane);
    float d_lo = __ldg(adst + lane);
    float a_hi = (lane < 8) ? __ldg(asrc + 32 + lane) : 0.f;
    float d_hi = (lane < 8) ? __ldg(adst + 32 + lane) : 0.f;
    #pragma unroll
    for (int rr = 0; rr < 16; rr++) {
        int row = wid * 16 + rr;
        int grow = brow + row;
        float v0 = Sh[row * 44 + lane];
        float v1 = (lane < 8) ? Sh[row * 44 + 32 + lane] : 0.f;
        float ps = v0 * a_lo + v1 * a_hi;
        float pd = v0 * d_lo + v1 * d_hi;
        #pragma unroll
        for (int o = 16; o >= 1; o >>= 1) {
            ps += __shfl_xor_sync(0xffffffffu, ps, o);
            pd += __shfl_xor_sync(0xffffffffu, pd, o);
        }
        if (lane == 0 && grow < NN) {
            g_esrc2[grow] = ps;
            g_edst2[grow] = pd;
            atomicMaxFShared(&smax2, ps);
        }
    }
    __syncthreads();
    if (tid == 0) atomicMaxF(&g_gmax2, __int_as_float(smax2));
}

// ---------------- GAT layer 2: shifted softmax + fp16 gather (x4 MLP) + log_softmax/softmax ----------------
__global__ void gat2_kernel(const float* __restrict__ bias, float* __restrict__ out) {
    int warp = (blockIdx.x * blockDim.x + threadIdx.x) >> 5;
    int lane = threadIdx.x & 31;
    if (blockIdx.x == 0) {
        if (threadIdx.x < 4) g_gmax1[threadIdx.x] = -1e30f;          // reset for next invocation
        else if (threadIdx.x < 7) g_bar[threadIdx.x - 4] = 0;         // reset grid barriers
    }
    if (warp >= NN) return;
    int d = warp;
    if (lane == 0) g_cnt[d] = 0;   // reset histogram for next invocation
    int base = g_rowptr[d];
    int end  = g_rowptr[d + 1];
    float ed = g_edst2[d];
    float S = lrelu(g_gmax2 + ed);

    float sumA = 0.f, sumB = 0.f;
    float a0A = 0.f, a1A = 0.f, a0B = 0.f, a1B = 0.f;
    int j = base;
    for (; j + 3 < end; j += 4) {
        int s0 = g_csrc[j];
        int s1 = g_csrc[j + 1];
        int s2 = g_csrc[j + 2];
        int s3 = g_csrc[j + 3];
        float es0 = g_esrc2[s0];
        float es1 = g_esrc2[s1];
        float es2 = g_esrc2[s2];
        float es3 = g_esrc2[s3];
        const __half* h0 = g_h2h + (size_t)s0 * NC;
        const __half* h1p = g_h2h + (size_t)s1 * NC;
        const __half* h2p = g_h2h + (size_t)s2 * NC;
        const __half* h3p = g_h2h + (size_t)s3 * NC;
        float f00 = __half2float(h0[lane]);
        float f10 = __half2float(h1p[lane]);
        float f20 = __half2float(h2p[lane]);
        float f30 = __half2float(h3p[lane]);
        float f01 = (lane < 8) ? __half2float(h0[32 + lane]) : 0.f;
        float f11 = (lane < 8) ? __half2float(h1p[32 + lane]) : 0.f;
        float f21 = (lane < 8) ? __half2float(h2p[32 + lane]) : 0.f;
        float f31 = (lane < 8) ? __half2float(h3p[32 + lane]) : 0.f;
        float w0 = __expf(lrelu(es0 + ed) - S);
        float w1 = __expf(lrelu(es1 + ed) - S);
        float w2 = __expf(lrelu(es2 + ed) - S);
        float w3 = __expf(lrelu(es3 + ed) - S);
        sumA += w0 + w2; sumB += w1 + w3;
        a0A += w0 * f00 + w2 * f20; a1A += w0 * f01 + w2 * f21;
        a0B += w1 * f10 + w3 * f30; a1B += w1 * f11 + w3 * f31;
    }
    for (; j < end; j++) {
        int s0 = g_csrc[j];
        float es0 = g_esrc2[s0];
        const __half* h0 = g_h2h + (size_t)s0 * NC;
        float w0 = __expf(lrelu(es0 + ed) - S);
        sumA += w0;
        a0A += w0 * __half2float(h0[lane]);
        if (lane < 8) a1A += w0 * __half2float(h0[32 + lane]);
    }
    float inv = 1.0f / (sumA + sumB + 1e-16f);
    float acc0 = (a0A + a0B) * inv;
    float acc1 = (a1A + a1B) * inv;

    float v0 = acc0 + __ldg(bias + lane);
    float v1 = (lane < 8) ? (acc1 + __ldg(bias + 32 + lane)) : -INFINITY;
    float m = fmaxf(v0, v1);
    #pragma unroll
    for (int o = 16; o >= 1; o >>= 1) m = fmaxf(m, __shfl_xor_sync(0xffffffffu, m, o));
    float e0 = expf(v0 - m);
    float e1 = (lane < 8) ? expf(v1 - m) : 0.f;
    float sm = e0 + e1;
    #pragma unroll
    for (int o = 16; o >= 1; o >>= 1) sm += __shfl_xor_sync(0xffffffffu, sm, o);
    float ls = logf(sm);
    float invs = 1.0f / sm;
    float* lo = out + (size_t)d * NC;
    float* so = out + (size_t)NN * NC + (size_t)d * NC;
    lo[lane] = v0 - m - ls;
    so[lane] = e0 * invs;
    if (lane < 8) {
        lo[32 + lane] = v1 - m - ls;
        so[32 + lane] = e1 * invs;
    }
}

// ---------------- launch ----------------
extern "C" void kernel_launch(void* const* d_in, const int* in_sizes, int n_in,
                              void* d_out, int out_size) {
    const float* x   = (const float*)d_in[0];
    const int*   ei  = (const int*)d_in[1];
    const float* W1  = (const float*)d_in[2];
    const float* as1 = (const float*)d_in[3];
    const float* ad1 = (const float*)d_in[4];
    const float* b1  = (const float*)d_in[5];
    const float* W2  = (const float*)d_in[6];
    const float* as2 = (const float*)d_in[7];
    const float* ad2 = (const float*)d_in[8];
    const float* b2  = (const float*)d_in[9];
    float* out = (float*)d_out;
    const int* src = ei;
    const int* dst = ei + NE;

    cudaFuncSetAttribute(fused1_kernel, cudaFuncAttributeMaxDynamicSharedMemorySize, G1_SMEM);
    cudaFuncSetAttribute(gemm2_kernel, cudaFuncAttributeMaxDynamicSharedMemorySize, G2_SMEM);

    fused1_kernel<<<CSRB + G1B, 256, G1_SMEM>>>(src, dst, x, W1, as1, ad1);
    gat1_kernel<<<6250, 256>>>(b1);
    gemm2_kernel<<<391, 256, G2_SMEM>>>(W2, as2, ad2);
    gat2_kernel<<<6250, 256>>>(b2, out);
}